// round 15
// baseline (speedup 1.0000x reference)
#include <cuda_runtime.h>
#include <cuda_bf16.h>
#include <math.h>
#include <stdint.h>

// ---------------- problem constants ----------------
#define Bq   8
#define Nseq 256
#define CS   512
#define Hh   8
#define Dd   64
#define NBb  65
#define CT   2048
#define ROWS 2048
#define CATC 1032
#define CATPAD 1088
#define OPOFF 520
#define X_ELEMS (ROWS*CS)

static const float WLv = 0.70710678118654752440f;         // sqrt(0.5)
static const float WLS = 0.70710678118654752440f / 8.0f;  // WL / sqrt(D)

// ---------------- scratch (device globals; no allocation) ----------------
__device__ float g_qkv [ROWS * 1536];    // [row][ q|k|v ], col = h*64+d  (head-major)
__device__ float g_embd[ROWS * CS];
__device__ float g_x1  [ROWS * CS];
__device__ float g_ff2 [ROWS * CS];

__device__ __nv_bfloat16 g_sh   [ROWS * CS],      g_sl   [ROWS * CS];
__device__ __nv_bfloat16 g_wqkvT_h[1536 * CS],    g_wqkvT_l[1536 * CS];
__device__ __nv_bfloat16 g_woT_h [CS * CATPAD],   g_woT_l [CS * CATPAD];
__device__ __nv_bfloat16 g_w1T_h [CT * CS],       g_w1T_l [CT * CS];
__device__ __nv_bfloat16 g_w2T_h [CS * CT],       g_w2T_l [CS * CT];
__device__ __nv_bfloat16 g_cath  [ROWS * CATPAD], g_catl  [ROWS * CATPAD];
__device__ __nv_bfloat16 g_x1h   [ROWS * CS],     g_x1l   [ROWS * CS];
__device__ __nv_bfloat16 g_ffh   [ROWS * CT],     g_ffl   [ROWS * CT];
__device__ __nv_bfloat16 g_ah    [64 * 256 * 256], g_al   [64 * 256 * 256]; // a hi/lo [bh][i][j]
__device__ __nv_bfloat16 g_vTh   [64 * 64 * 256],  g_vTl  [64 * 64 * 256];  // vT hi/lo [bh][d][j]

// ---------------- low-level helpers ----------------
__device__ __forceinline__ uint32_t smem_to_u32(const void* p) {
    uint32_t a;
    asm("{ .reg .u64 t; cvta.to.shared.u64 t, %1; cvt.u32.u64 %0, t; }" : "=r"(a) : "l"(p));
    return a;
}
__device__ __forceinline__ void cp_async16(uint32_t dst, const void* src) {
    asm volatile("cp.async.cg.shared.global [%0], [%1], 16;" :: "r"(dst), "l"(src));
}
#define CP_COMMIT() asm volatile("cp.async.commit_group;" ::: "memory")
#define CP_WAIT1()  asm volatile("cp.async.wait_group 1;" ::: "memory")

__device__ __forceinline__ void ldsm4(uint32_t* r, uint32_t addr) {
    asm volatile("ldmatrix.sync.aligned.m8n8.x4.shared.b16 {%0,%1,%2,%3}, [%4];"
        : "=r"(r[0]), "=r"(r[1]), "=r"(r[2]), "=r"(r[3]) : "r"(addr));
}
__device__ __forceinline__ void mma16816(float* c, const uint32_t* a, const uint32_t* b) {
    asm volatile("mma.sync.aligned.m16n8k16.row.col.f32.bf16.bf16.f32 "
        "{%0,%1,%2,%3}, {%4,%5,%6,%7}, {%8,%9}, {%0,%1,%2,%3};"
        : "+f"(c[0]), "+f"(c[1]), "+f"(c[2]), "+f"(c[3])
        : "r"(a[0]), "r"(a[1]), "r"(a[2]), "r"(a[3]), "r"(b[0]), "r"(b[1]));
}
__device__ __forceinline__ void bf16pair(float v, __nv_bfloat16& h, __nv_bfloat16& l) {
    h = __float2bfloat16(v);
    l = __float2bfloat16(v - __bfloat162float(h));
}

// ---------------- shared GEMM machinery ----------------
#define SKP 40
#define A_ARR (128 * SKP * 2)
#define B_ARR (64 * SKP * 2)
#define STAGE_B (2 * A_ARR + 2 * B_ARR)
#define NSTAGE 3

template<int NT>
__device__ __forceinline__ void gemm_load_stage(
    uint32_t stage, const __nv_bfloat16* Ah, const __nv_bfloat16* Al,
    const __nv_bfloat16* Bh, const __nv_bfloat16* Bl,
    int m0, int n0, int Ktot, int k0, int t, int ldk)
{
#pragma unroll
    for (int p = 0; p < 2; p++) {
        int id = t + p * 256;
        int r = id >> 2;
        cp_async16(stage + 0 * A_ARR + (uint32_t)(r * SKP + ldk) * 2,
                   Ah + (size_t)(m0 + r) * Ktot + k0 + ldk);
        cp_async16(stage + 1 * A_ARR + (uint32_t)(r * SKP + ldk) * 2,
                   Al + (size_t)(m0 + r) * Ktot + k0 + ldk);
    }
    {
        int r = t >> 2;
        cp_async16(stage + 2 * A_ARR + (uint32_t)(r * SKP + ldk) * 2,
                   Bh + (size_t)(n0 + r) * Ktot + k0 + ldk);
        if (NT == 3)
            cp_async16(stage + 2 * A_ARR + B_ARR + (uint32_t)(r * SKP + ldk) * 2,
                       Bl + (size_t)(n0 + r) * Ktot + k0 + ldk);
    }
}

template<int NT>
__device__ __forceinline__ void gemm_mainloop(
    uint32_t sb, const __nv_bfloat16* Ah, const __nv_bfloat16* Al,
    const __nv_bfloat16* Bh, const __nv_bfloat16* Bl,
    int m0, int n0, int Ktot, int t, float acc[2][4][4],
    uint32_t aRowOff, uint32_t bRowOff)
{
    const int ldk = (t & 3) * 8;
    const int nch = Ktot >> 5;

    gemm_load_stage<NT>(sb, Ah, Al, Bh, Bl, m0, n0, Ktot, 0, t, ldk);
    CP_COMMIT();
    if (nch > 1) gemm_load_stage<NT>(sb + STAGE_B, Ah, Al, Bh, Bl, m0, n0, Ktot, 32, t, ldk);
    CP_COMMIT();

    int sidx = 0;
    for (int c = 0; c < nch; c++) {
        CP_WAIT1();
        __syncthreads();

        if (c + 2 < nch) {
            int fidx = sidx + 2; if (fidx >= NSTAGE) fidx -= NSTAGE;
            gemm_load_stage<NT>(sb + fidx * STAGE_B, Ah, Al, Bh, Bl, m0, n0, Ktot, (c + 2) << 5, t, ldk);
        }
        CP_COMMIT();

        const uint32_t stage = sb + sidx * STAGE_B;
#pragma unroll
        for (int kk = 0; kk < 2; kk++) {
            const uint32_t kO = kk * 32;
            uint32_t aH[2][4], aL[2][4], bH[4][2], bL[4][2];
#pragma unroll
            for (int mt = 0; mt < 2; mt++) {
                ldsm4(aH[mt], stage + 0 * A_ARR + aRowOff + (uint32_t)(mt * 16 * SKP) * 2 + kO);
                ldsm4(aL[mt], stage + 1 * A_ARR + aRowOff + (uint32_t)(mt * 16 * SKP) * 2 + kO);
            }
#pragma unroll
            for (int nt2 = 0; nt2 < 2; nt2++) {
                uint32_t base = (uint32_t)((nt2 * 16) * SKP) * 2 + bRowOff + kO;
                ldsm4(&bH[nt2 * 2][0], stage + 2 * A_ARR + base);
                if (NT == 3) ldsm4(&bL[nt2 * 2][0], stage + 2 * A_ARR + B_ARR + base);
            }
#pragma unroll
            for (int mt = 0; mt < 2; mt++)
#pragma unroll
                for (int nt = 0; nt < 4; nt++)
                    mma16816(acc[mt][nt], aH[mt], bH[nt]);
#pragma unroll
            for (int mt = 0; mt < 2; mt++)
#pragma unroll
                for (int nt = 0; nt < 4; nt++)
                    mma16816(acc[mt][nt], aL[mt], bH[nt]);
            if (NT == 3) {
#pragma unroll
                for (int mt = 0; mt < 2; mt++)
#pragma unroll
                    for (int nt = 0; nt < 4; nt++)
                        mma16816(acc[mt][nt], aH[mt], bL[nt]);
            }
        }

        if (++sidx == NSTAGE) sidx = 0;
    }
}

// general GEMM; mode 0: fp32 out (+bias); mode 2: relu -> bf16 pair
template<int NT>
__global__ __launch_bounds__(256, 2)
void mma_gemm(const __nv_bfloat16* __restrict__ Ah, const __nv_bfloat16* __restrict__ Al,
              const __nv_bfloat16* __restrict__ Bh, const __nv_bfloat16* __restrict__ Bl,
              const float* __restrict__ bias,
              float* __restrict__ Cf, __nv_bfloat16* __restrict__ Ch, __nv_bfloat16* __restrict__ Cl,
              int Ktot, int ldc, int mode)
{
    extern __shared__ __align__(128) char smemc[];
    const uint32_t sb = smem_to_u32(smemc);
    const int t = threadIdx.x, w = t >> 5, lane = t & 31;
    const int m0 = blockIdx.y * 128, n0 = blockIdx.x * 64;
    const int wm = w & 3, wn = w >> 2;

    const uint32_t aRowOff = (uint32_t)((wm * 32 + (lane & 15)) * SKP + (lane >> 4) * 8) * 2;
    const uint32_t bRowOff = (uint32_t)((wn * 32 + (lane >> 4) * 8 + (lane & 7)) * SKP + ((lane >> 3) & 1) * 8) * 2;

    float acc[2][4][4];
#pragma unroll
    for (int i = 0; i < 2; i++)
#pragma unroll
        for (int j = 0; j < 4; j++)
#pragma unroll
            for (int x = 0; x < 4; x++) acc[i][j][x] = 0.f;

    gemm_mainloop<NT>(sb, Ah, Al, Bh, Bl, m0, n0, Ktot, t, acc, aRowOff, bRowOff);

    const int rbase = m0 + wm * 32 + (lane >> 2);
    const int cbase = n0 + wn * 32 + (lane & 3) * 2;
#pragma unroll
    for (int mt = 0; mt < 2; mt++)
#pragma unroll
        for (int half = 0; half < 2; half++) {
            const int m = rbase + mt * 16 + half * 8;
#pragma unroll
            for (int nt = 0; nt < 4; nt++) {
                const int n = cbase + nt * 8;
                float v0 = acc[mt][nt][half * 2 + 0];
                float v1 = acc[mt][nt][half * 2 + 1];
                if (bias) { v0 += bias[n]; v1 += bias[n + 1]; }
                if (mode == 2) {
                    v0 = fmaxf(v0, 0.f); v1 = fmaxf(v1, 0.f);
                    __nv_bfloat16 h0, l0, h1, l1;
                    bf16pair(v0, h0, l0); bf16pair(v1, h1, l1);
                    *(__nv_bfloat162*)(Ch + (size_t)m * ldc + n) = __nv_bfloat162(h0, h1);
                    *(__nv_bfloat162*)(Cl + (size_t)m * ldc + n) = __nv_bfloat162(l0, l1);
                } else {
                    *(float2*)(Cf + (size_t)m * ldc + n) = make_float2(v0, v1);
                }
            }
        }
}

// batched ov GEMM: o[bh][128x64] = a[bh][128x256] @ vT[bh][64x256]^T, 3-term, cat epilogue
__global__ __launch_bounds__(256, 2)
void attn_ov_mma(const __nv_bfloat16* __restrict__ a_h, const __nv_bfloat16* __restrict__ a_l,
                 const __nv_bfloat16* __restrict__ vTh, const __nv_bfloat16* __restrict__ vTl,
                 __nv_bfloat16* __restrict__ cath, __nv_bfloat16* __restrict__ catl)
{
    extern __shared__ __align__(128) char smemc[];
    const uint32_t sb = smem_to_u32(smemc);
    const int t = threadIdx.x, w = t >> 5, lane = t & 31;
    const int bh = blockIdx.x, it = blockIdx.y;
    const int b = bh >> 3, h = bh & 7;
    const int m0 = it * 128;
    const int wm = w & 3, wn = w >> 2;

    const __nv_bfloat16* Ah = a_h + (size_t)bh * 256 * 256;
    const __nv_bfloat16* Al = a_l + (size_t)bh * 256 * 256;
    const __nv_bfloat16* Bh = vTh + (size_t)bh * 64 * 256;
    const __nv_bfloat16* Bl = vTl + (size_t)bh * 64 * 256;

    const uint32_t aRowOff = (uint32_t)((wm * 32 + (lane & 15)) * SKP + (lane >> 4) * 8) * 2;
    const uint32_t bRowOff = (uint32_t)((wn * 32 + (lane >> 4) * 8 + (lane & 7)) * SKP + ((lane >> 3) & 1) * 8) * 2;

    float acc[2][4][4];
#pragma unroll
    for (int i = 0; i < 2; i++)
#pragma unroll
        for (int j = 0; j < 4; j++)
#pragma unroll
            for (int x = 0; x < 4; x++) acc[i][j][x] = 0.f;

    gemm_mainloop<3>(sb, Ah, Al, Bh, Bl, m0, 0, 256, t, acc, aRowOff, bRowOff);

    const int rbase = m0 + wm * 32 + (lane >> 2);
    const int cbase = wn * 32 + (lane & 3) * 2;
#pragma unroll
    for (int mt = 0; mt < 2; mt++)
#pragma unroll
        for (int half = 0; half < 2; half++) {
            const int i = rbase + mt * 16 + half * 8;
#pragma unroll
            for (int nt = 0; nt < 4; nt++) {
                const int d = cbase + nt * 8;
                size_t off = (size_t)(b * Nseq + i) * CATPAD + OPOFF + h * Dd + d;
                __nv_bfloat16 h0, l0, h1, l1;
                bf16pair(acc[mt][nt][half * 2 + 0], h0, l0);
                bf16pair(acc[mt][nt][half * 2 + 1], h1, l1);
                *(__nv_bfloat162*)(cath + off) = __nv_bfloat162(h0, h1);
                *(__nv_bfloat162*)(catl + off) = __nv_bfloat162(l0, l1);
            }
        }
}

// vT transpose-convert: fp32 v [row][1024 + h*64 + d] -> bf16 pair [bh][d][j]
// grid (64, 8): bh, j-block of 32. threads 256.
__global__ __launch_bounds__(256)
void vT_cvt(const float* __restrict__ qkv,
            __nv_bfloat16* __restrict__ vTh, __nv_bfloat16* __restrict__ vTl)
{
    __shared__ float tile[64][33];
    const int bh = blockIdx.x, jb = blockIdx.y;
    const int b = bh >> 3, h = bh & 7;
    const int t = threadIdx.x;
    const int j0 = jb * 32;

    const float* vbase = qkv + (size_t)b * Nseq * 1536 + 1024 + h * 64;
#pragma unroll
    for (int p = 0; p < 8; p++) {
        int idx = t + p * 256;
        int j = idx >> 6, d = idx & 63;      // coalesced along d
        tile[d][j] = vbase[(size_t)(j0 + j) * 1536 + d];
    }
    __syncthreads();
#pragma unroll
    for (int p = 0; p < 8; p++) {
        int idx = t + p * 256;
        int d = idx >> 5, j = idx & 31;      // coalesced along j
        __nv_bfloat16 hh, ll; bf16pair(tile[d][j], hh, ll);
        size_t off = ((size_t)bh * 64 + d) * 256 + j0 + j;
        vTh[off] = hh; vTl[off] = ll;
    }
}

// ---------------- fused prep ----------------
struct PrepJob {
    const float* src; __nv_bfloat16 *dh, *dl;
    int K, Nn, Kpad, ktiles, perm, base; float scale;
};
struct PrepArgs {
    PrepJob j[6];
    const float4* s_src; __nv_bfloat162 *s_dh, *s_dl;
    __nv_bfloat16 *pad_h, *pad_l;
    int cvt_base, pad_base;
};

__global__ void prep_kernel(PrepArgs a)
{
    __shared__ float tile[32][33];
    const int bid = blockIdx.x;
    const int tx = threadIdx.x, ty = threadIdx.y;
    const int t = ty * 32 + tx;

    if (bid >= a.pad_base) {
        int idx = (bid - a.pad_base) * 256 + t;
        int row = idx / (CATPAD - CATC), col = idx % (CATPAD - CATC);
        if (row < ROWS) {
            a.pad_h[(size_t)row * CATPAD + CATC + col] = __float2bfloat16(0.f);
            a.pad_l[(size_t)row * CATPAD + CATC + col] = __float2bfloat16(0.f);
        }
        return;
    }
    if (bid >= a.cvt_base) {
        int i = (bid - a.cvt_base) * 256 + t;
        float4 v = a.s_src[i];
        __nv_bfloat16 hx, lx, hy, ly, hz, lz, hw, lw;
        bf16pair(v.x, hx, lx); bf16pair(v.y, hy, ly);
        bf16pair(v.z, hz, lz); bf16pair(v.w, hw, lw);
        a.s_dh[i * 2 + 0] = __nv_bfloat162(hx, hy); a.s_dh[i * 2 + 1] = __nv_bfloat162(hz, hw);
        a.s_dl[i * 2 + 0] = __nv_bfloat162(lx, ly); a.s_dl[i * 2 + 1] = __nv_bfloat162(lz, lw);
        return;
    }

    int ji = 0;
#pragma unroll
    for (int q = 1; q < 6; q++) if (bid >= a.j[q].base) ji = q;
    const PrepJob jb = a.j[ji];
    const int local = bid - jb.base;
    const int kt = local % jb.ktiles, ntl = local / jb.ktiles;
    const int k0 = kt * 32, n0 = ntl * 32;

#pragma unroll
    for (int j = 0; j < 4; j++) {
        int k = k0 + ty + j * 8;
        int n = n0 + tx;
        tile[tx][ty + j * 8] = (k < jb.K) ? jb.src[(size_t)k * jb.Nn + n] * jb.scale : 0.f;
    }
    __syncthreads();
#pragma unroll
    for (int j = 0; j < 4; j++) {
        int k = k0 + tx;
        int n = n0 + ty + j * 8;
        int nr = jb.perm ? (((n & 7) << 6) | (n >> 3)) : n;
        float v = tile[ty + j * 8][tx];
        __nv_bfloat16 h, l; bf16pair(v, h, l);
        jb.dh[(size_t)nr * jb.Kpad + k] = h;
        jb.dl[(size_t)nr * jb.Kpad + k] = l;
    }
}

// ---------------- attention softmax (register tiled) ----------------
#define KTS 260
#define QSS 68

__global__ __launch_bounds__(256, 2)
void attn_softmax_kernel(const float* __restrict__ qkv, const float* __restrict__ wb,
                         float* __restrict__ a_out,
                         __nv_bfloat16* __restrict__ a_h, __nv_bfloat16* __restrict__ a_l,
                         __nv_bfloat16* __restrict__ cath, __nv_bfloat16* __restrict__ catl)
{
    extern __shared__ float sm[];
    float* qs   = sm;
    float* kT   = qs + 64 * QSS;
    float* wbs  = kT + 64 * KTS;
    float* pinv = wbs + 68;
    float* p0   = pinv + 64;
    float* p1   = p0 + 64;

    const int bh = blockIdx.x, it = blockIdx.y;
    const int b = bh >> 3, h = bh & 7;
    const int t = threadIdx.x;
    const int tn = t & 15, tm = t >> 4;
    const int i0 = it * 64;

    const float* base = qkv + (size_t)b * Nseq * 1536 + h * 64;

#pragma unroll
    for (int p = 0; p < 4; p++) {
        int idx = t + p * 256;
        int r = idx >> 4, dg = idx & 15;
        float4 v = *(const float4*)(base + (size_t)(i0 + r) * 1536 + dg * 4);
        *(float4*)&qs[r * QSS + dg * 4] = v;
    }
#pragma unroll
    for (int p = 0; p < 16; p++) {
        int j = (t >> 4) + p * 16;
        int dg = t & 15;
        float4 v = *(const float4*)(base + (size_t)j * 1536 + 512 + dg * 4);
        kT[(dg * 4 + 0) * KTS + j] = v.x;
        kT[(dg * 4 + 1) * KTS + j] = v.y;
        kT[(dg * 4 + 2) * KTS + j] = v.z;
        kT[(dg * 4 + 3) * KTS + j] = v.w;
    }
    if (t < NBb) wbs[t] = WLv * wb[t * Hh + h];
    __syncthreads();

    float acc[4][16];
#pragma unroll
    for (int x = 0; x < 4; x++)
#pragma unroll
        for (int u = 0; u < 16; u++) acc[x][u] = 0.f;

#pragma unroll 4
    for (int d = 0; d < 64; d++) {
        float a0 = qs[(tm * 4 + 0) * QSS + d];
        float a1 = qs[(tm * 4 + 1) * QSS + d];
        float a2 = qs[(tm * 4 + 2) * QSS + d];
        float a3 = qs[(tm * 4 + 3) * QSS + d];
        const float* kr = &kT[d * KTS + tn * 16];
        float4 b0 = *(const float4*)(kr + 0);
        float4 b1 = *(const float4*)(kr + 4);
        float4 b2 = *(const float4*)(kr + 8);
        float4 b3 = *(const float4*)(kr + 12);
        const float bv[16] = { b0.x,b0.y,b0.z,b0.w, b1.x,b1.y,b1.z,b1.w,
                               b2.x,b2.y,b2.z,b2.w, b3.x,b3.y,b3.z,b3.w };
#pragma unroll
        for (int u = 0; u < 16; u++) {
            acc[0][u] += a0 * bv[u];
            acc[1][u] += a1 * bv[u];
            acc[2][u] += a2 * bv[u];
            acc[3][u] += a3 * bv[u];
        }
    }

#pragma unroll
    for (int x = 0; x < 4; x++) {
        const int i = i0 + tm * 4 + x;
#pragma unroll
        for (int u = 0; u < 16; u++) {
            int c = i - (tn * 16 + u);
            c = (c < -32) ? -32 : (c > 32 ? 32 : c);
            acc[x][u] += wbs[c + 32];
        }
    }

    float inv4[4], s04[4], s14[4];
#pragma unroll
    for (int x = 0; x < 4; x++) {
        const int i = i0 + tm * 4 + x;
        float m = acc[x][0];
#pragma unroll
        for (int u = 1; u < 16; u++) m = fmaxf(m, acc[x][u]);
#pragma unroll
        for (int o = 1; o < 16; o <<= 1) m = fmaxf(m, __shfl_xor_sync(0xffffffffu, m, o));
        float se = 0.f, s0 = 0.f, s1 = 0.f;
#pragma unroll
        for (int u = 0; u < 16; u++) {
            float e = __expf(acc[x][u] - m);
            acc[x][u] = e;
            se += e;
            int j = tn * 16 + u;
            if (j >= i + 32) s0 += e;
            if (j <= i - 32) s1 += e;
        }
#pragma unroll
        for (int o = 1; o < 16; o <<= 1) {
            se += __shfl_xor_sync(0xffffffffu, se, o);
            s0 += __shfl_xor_sync(0xffffffffu, s0, o);
            s1 += __shfl_xor_sync(0xffffffffu, s1, o);
        }
        float inv = 1.f / se;
        inv4[x] = inv; s04[x] = s0 * inv; s14[x] = s1 * inv;
    }

    __syncthreads();

    float* ls = kT;
#pragma unroll
    for (int x = 0; x < 4; x++) {
        const int r = tm * 4 + x;
        const int i = i0 + r;
        const float inv = inv4[x];
        *(float4*)&ls[r * KTS + tn * 16 + 0]  = make_float4(acc[x][0], acc[x][1], acc[x][2], acc[x][3]);
        *(float4*)&ls[r * KTS + tn * 16 + 4]  = make_float4(acc[x][4], acc[x][5], acc[x][6], acc[x][7]);
        *(float4*)&ls[r * KTS + tn * 16 + 8]  = make_float4(acc[x][8], acc[x][9], acc[x][10], acc[x][11]);
        *(float4*)&ls[r * KTS + tn * 16 + 12] = make_float4(acc[x][12], acc[x][13], acc[x][14], acc[x][15]);
        float av[16];
#pragma unroll
        for (int u = 0; u < 16; u++) av[u] = acc[x][u] * inv;
        float* ar = a_out + ((size_t)bh * 256 + i) * 256 + tn * 16;
        *(float4*)(ar + 0)  = make_float4(av[0], av[1], av[2], av[3]);
        *(float4*)(ar + 4)  = make_float4(av[4], av[5], av[6], av[7]);
        *(float4*)(ar + 8)  = make_float4(av[8], av[9], av[10], av[11]);
        *(float4*)(ar + 12) = make_float4(av[12], av[13], av[14], av[15]);
        size_t ao = ((size_t)bh * 256 + i) * 256 + tn * 16;
#pragma unroll
        for (int u = 0; u < 16; u += 2) {
            __nv_bfloat16 h0, l0, h1, l1;
            bf16pair(av[u], h0, l0); bf16pair(av[u + 1], h1, l1);
            *(__nv_bfloat162*)(a_h + ao + u) = __nv_bfloat162(h0, h1);
            *(__nv_bfloat162*)(a_l + ao + u) = __nv_bfloat162(l0, l1);
        }
        if (tn == 0) { pinv[r] = inv; p0[r] = s04[x]; p1[r] = s14[x]; }
    }
    __syncthreads();

    // phase 3: all 256 threads cover 64 rows x 65 bins
#pragma unroll
    for (int p = 0; p < 17; p++) {
        int idx = t + p * 256;
        if (idx < 64 * NBb) {
            int r = idx / NBb, c = idx - r * NBb;
            const int i = i0 + r;
            float val;
            if (c == 0)       val = p0[r];
            else if (c == 64) val = p1[r];
            else {
                int j = i + 32 - c;
                val = (j >= 0 && j < 256) ? ls[r * KTS + j] * pinv[r] : 0.f;
            }
            __nv_bfloat16 hh, ll; bf16pair(val, hh, ll);
            size_t off = (size_t)(b * Nseq + i) * CATPAD + h * NBb + c;
            cath[off] = hh; catl[off] = ll;
        }
    }
}

// ---------------- layernorm ----------------
__global__ __launch_bounds__(256)
void ln_kernel(const float* __restrict__ xa, const float* __restrict__ xb,
               const float* __restrict__ g, const float* __restrict__ be,
               float* __restrict__ out, __nv_bfloat16* __restrict__ oh, __nv_bfloat16* __restrict__ ol)
{
    __shared__ float red[16];
    const int row = blockIdx.x, t = threadIdx.x;
    const float* pa = xa + (size_t)row * CS;
    const float* pb = xb + (size_t)row * CS;
    float x0 = pa[t] + pb[t];
    float x1 = pa[t + 256] + pb[t + 256];
    float s = x0 + x1, q = x0 * x0 + x1 * x1;
    const int lane = t & 31, w = t >> 5;
#pragma unroll
    for (int o = 16; o; o >>= 1) {
        s += __shfl_xor_sync(0xffffffffu, s, o);
        q += __shfl_xor_sync(0xffffffffu, q, o);
    }
    if (lane == 0) { red[w] = s; red[8 + w] = q; }
    __syncthreads();
    float S = 0.f, Q = 0.f;
#pragma unroll
    for (int u = 0; u < 8; u++) { S += red[u]; Q += red[8 + u]; }
    float mean = S * (1.f / 512.f);
    float var  = Q * (1.f / 512.f) - mean * mean;
    float rstd = rsqrtf(var + 1e-5f);
    float y0 = (x0 - mean) * rstd * g[t] + be[t];
    float y1 = (x1 - mean) * rstd * g[t + 256] + be[t + 256];
    out[(size_t)row * CS + t]       = y0;
    out[(size_t)row * CS + t + 256] = y1;
    if (oh) {
        __nv_bfloat16 h, l;
        bf16pair(y0, h, l); oh[(size_t)row * CS + t] = h;       ol[(size_t)row * CS + t] = l;
        bf16pair(y1, h, l); oh[(size_t)row * CS + t + 256] = h; ol[(size_t)row * CS + t + 256] = l;
    }
}

// ---------------- launch ----------------
extern "C" void kernel_launch(void* const* d_in, const int* in_sizes, int n_in,
                              void* d_out, int out_size)
{
    const float* s     = (const float*)d_in[0];
    const float* wq    = (const float*)d_in[2];
    const float* wk    = (const float*)d_in[3];
    const float* wv    = (const float*)d_in[4];
    const float* wb    = (const float*)d_in[5];
    const float* wo    = (const float*)d_in[6];
    const float* bo    = (const float*)d_in[7];
    const float* ln1g  = (const float*)d_in[8];
    const float* ln1b  = (const float*)d_in[9];
    const float* w1    = (const float*)d_in[10];
    const float* b1    = (const float*)d_in[11];
    const float* w2    = (const float*)d_in[12];
    const float* b2    = (const float*)d_in[13];
    const float* ln2g  = (const float*)d_in[14];
    const float* ln2b  = (const float*)d_in[15];

    float* out   = (float*)d_out;
    float* a_out = out + X_ELEMS;

    float *p_qkv, *p_embd, *p_x1, *p_ff2;
    __nv_bfloat16 *p_sh, *p_sl, *p_wqkvh, *p_wqkvl, *p_woh, *p_wol, *p_w1h, *p_w1l,
                  *p_w2h, *p_w2l, *p_cath, *p_catl, *p_x1h, *p_x1l, *p_ffh, *p_ffl,
                  *p_ah, *p_al, *p_vTh, *p_vTl;
    cudaGetSymbolAddress((void**)&p_qkv,   g_qkv);
    cudaGetSymbolAddress((void**)&p_embd,  g_embd);
    cudaGetSymbolAddress((void**)&p_x1,    g_x1);
    cudaGetSymbolAddress((void**)&p_ff2,   g_ff2);
    cudaGetSymbolAddress((void**)&p_sh,    g_sh);
    cudaGetSymbolAddress((void**)&p_sl,    g_sl);
    cudaGetSymbolAddress((void**)&p_wqkvh, g_wqkvT_h);
    cudaGetSymbolAddress((void**)&p_wqkvl, g_wqkvT_l);
    cudaGetSymbolAddress((void**)&p_woh,   g_woT_h);
    cudaGetSymbolAddress((void**)&p_wol,   g_woT_l);
    cudaGetSymbolAddress((void**)&p_w1h,   g_w1T_h);
    cudaGetSymbolAddress((void**)&p_w1l,   g_w1T_l);
    cudaGetSymbolAddress((void**)&p_w2h,   g_w2T_h);
    cudaGetSymbolAddress((void**)&p_w2l,   g_w2T_l);
    cudaGetSymbolAddress((void**)&p_cath,  g_cath);
    cudaGetSymbolAddress((void**)&p_catl,  g_catl);
    cudaGetSymbolAddress((void**)&p_x1h,   g_x1h);
    cudaGetSymbolAddress((void**)&p_x1l,   g_x1l);
    cudaGetSymbolAddress((void**)&p_ffh,   g_ffh);
    cudaGetSymbolAddress((void**)&p_ffl,   g_ffl);
    cudaGetSymbolAddress((void**)&p_ah,    g_ah);
    cudaGetSymbolAddress((void**)&p_al,    g_al);
    cudaGetSymbolAddress((void**)&p_vTh,   g_vTh);
    cudaGetSymbolAddress((void**)&p_vTl,   g_vTl);

    const int SM1 = (64 * QSS + 64 * KTS + 68 + 192) * 4;
    const int SMG = NSTAGE * STAGE_B;   // 92,160
    cudaFuncSetAttribute(attn_softmax_kernel, cudaFuncAttributeMaxDynamicSharedMemorySize, SM1);
    cudaFuncSetAttribute(attn_ov_mma,         cudaFuncAttributeMaxDynamicSharedMemorySize, SMG);
    cudaFuncSetAttribute(mma_gemm<3>,         cudaFuncAttributeMaxDynamicSharedMemorySize, SMG);
    cudaFuncSetAttribute(mma_gemm<2>,         cudaFuncAttributeMaxDynamicSharedMemorySize, SMG);

    dim3 blk(256);

    // fused prep (ONE launch)
    PrepArgs pa;
    pa.j[0] = { wq, p_wqkvh,              p_wqkvl,              512,  512,  512, 16, 1, 0,    WLS };
    pa.j[1] = { wk, p_wqkvh + 512 * 512,  p_wqkvl + 512 * 512,  512,  512,  512, 16, 1, 256,  1.f };
    pa.j[2] = { wv, p_wqkvh + 1024 * 512, p_wqkvl + 1024 * 512, 512,  512,  512, 16, 1, 512,  1.f };
    pa.j[3] = { wo, p_woh,  p_wol,  CATC, 512,  CATPAD, 34, 0, 768,  1.f };
    pa.j[4] = { w1, p_w1h,  p_w1l,  512,  CT,   512,    16, 0, 1312, 1.f };
    pa.j[5] = { w2, p_w2h,  p_w2l,  CT,   512,  CT,     64, 0, 2336, 1.f };
    pa.s_src = (const float4*)s;
    pa.s_dh  = (__nv_bfloat162*)p_sh;
    pa.s_dl  = (__nv_bfloat162*)p_sl;
    pa.pad_h = p_cath; pa.pad_l = p_catl;
    pa.cvt_base = 3360;
    pa.pad_base = 3360 + 1024;
    prep_kernel<<<3360 + 1024 + 448, dim3(32, 8)>>>(pa);

    // qkv = s @ [wq|wk|wv]  — 2-term, clean fp32 epilogue
    mma_gemm<2><<<dim3(24, 16), blk, SMG>>>(p_sh, p_sl, p_wqkvh, p_wqkvl, nullptr,
                                            p_qkv, nullptr, nullptr, 512, 1536, 0);

    // vT = transpose-convert of v section (coalesced both sides)
    vT_cvt<<<dim3(64, 8), blk>>>(p_qkv, p_vTh, p_vTl);

    // attention: softmax (emits a fp32 + a bf16 pair + o_pair) then HMMA ov
    attn_softmax_kernel<<<dim3(Bq * Hh, 4), blk, SM1>>>(p_qkv, wb, a_out, p_ah, p_al, p_cath, p_catl);
    attn_ov_mma<<<dim3(Bq * Hh, 2), blk, SMG>>>(p_ah, p_al, p_vTh, p_vTl, p_cath, p_catl);

    // embd = cat @ wo + bo — 2-term
    mma_gemm<2><<<dim3(8, 16), blk, SMG>>>(p_cath, p_catl, p_woh, p_wol, bo,
                                           p_embd, nullptr, nullptr, CATPAD, 512, 0);

    // x1 = LN(s + embd)
    ln_kernel<<<ROWS, blk>>>(s, p_embd, ln1g, ln1b, p_x1, p_x1h, p_x1l);

    // ff = relu(x1 @ w1 + b1) — 2-term
    mma_gemm<2><<<dim3(32, 16), blk, SMG>>>(p_x1h, p_x1l, p_w1h, p_w1l, b1,
                                            nullptr, p_ffh, p_ffl, 512, CT, 2);

    // ff2 = ff @ w2 + b2 — 2-term
    mma_gemm<2><<<dim3(8, 16), blk, SMG>>>(p_ffh, p_ffl, p_w2h, p_w2l, b2,
                                           p_ff2, nullptr, nullptr, CT, 512, 0);

    // out = LN(x1 + ff2)
    ln_kernel<<<ROWS, blk>>>(p_x1, p_ff2, ln2g, ln2b, out, nullptr, nullptr);
}

// round 16
// speedup vs baseline: 1.0852x; 1.0852x over previous
#include <cuda_runtime.h>
#include <cuda_bf16.h>
#include <math.h>
#include <stdint.h>

// ---------------- problem constants ----------------
#define Bq   8
#define Nseq 256
#define CS   512
#define Hh   8
#define Dd   64
#define NBb  65
#define CT   2048
#define ROWS 2048
#define CATC 1032
#define CATPAD 1088
#define OPOFF 520
#define X_ELEMS (ROWS*CS)

static const float WLv = 0.70710678118654752440f;         // sqrt(0.5)
static const float WLS = 0.70710678118654752440f / 8.0f;  // WL / sqrt(D)

// ---------------- scratch (device globals; no allocation) ----------------
__device__ float g_qkv [ROWS * 1536];    // [row][ q|k|v ], col = h*64+d  (head-major)
__device__ float g_embd[ROWS * CS];
__device__ float g_x1  [ROWS * CS];
__device__ float g_ff2 [ROWS * CS];

__device__ __nv_bfloat16 g_sh   [ROWS * CS],      g_sl   [ROWS * CS];
__device__ __nv_bfloat16 g_wqkvT_h[1536 * CS],    g_wqkvT_l[1536 * CS];
__device__ __nv_bfloat16 g_woT_h [CS * CATPAD],   g_woT_l [CS * CATPAD];
__device__ __nv_bfloat16 g_w1T_h [CT * CS],       g_w1T_l [CT * CS];
__device__ __nv_bfloat16 g_w2T_h [CS * CT],       g_w2T_l [CS * CT];
__device__ __nv_bfloat16 g_cath  [ROWS * CATPAD], g_catl  [ROWS * CATPAD];
__device__ __nv_bfloat16 g_x1h   [ROWS * CS],     g_x1l   [ROWS * CS];
__device__ __nv_bfloat16 g_ffh   [ROWS * CT],     g_ffl   [ROWS * CT];
__device__ __nv_bfloat16 g_ah    [64 * 256 * 256], g_al   [64 * 256 * 256]; // a hi/lo [bh][i][j]
__device__ __nv_bfloat16 g_vTh   [64 * 64 * 256],  g_vTl  [64 * 64 * 256];  // vT hi/lo [bh][d][j]

// ---------------- low-level helpers ----------------
__device__ __forceinline__ uint32_t smem_to_u32(const void* p) {
    uint32_t a;
    asm("{ .reg .u64 t; cvta.to.shared.u64 t, %1; cvt.u32.u64 %0, t; }" : "=r"(a) : "l"(p));
    return a;
}
__device__ __forceinline__ void cp_async16(uint32_t dst, const void* src) {
    asm volatile("cp.async.cg.shared.global [%0], [%1], 16;" :: "r"(dst), "l"(src));
}
#define CP_COMMIT() asm volatile("cp.async.commit_group;" ::: "memory")
#define CP_WAIT1()  asm volatile("cp.async.wait_group 1;" ::: "memory")

__device__ __forceinline__ void ldsm4(uint32_t* r, uint32_t addr) {
    asm volatile("ldmatrix.sync.aligned.m8n8.x4.shared.b16 {%0,%1,%2,%3}, [%4];"
        : "=r"(r[0]), "=r"(r[1]), "=r"(r[2]), "=r"(r[3]) : "r"(addr));
}
__device__ __forceinline__ void mma16816(float* c, const uint32_t* a, const uint32_t* b) {
    asm volatile("mma.sync.aligned.m16n8k16.row.col.f32.bf16.bf16.f32 "
        "{%0,%1,%2,%3}, {%4,%5,%6,%7}, {%8,%9}, {%0,%1,%2,%3};"
        : "+f"(c[0]), "+f"(c[1]), "+f"(c[2]), "+f"(c[3])
        : "r"(a[0]), "r"(a[1]), "r"(a[2]), "r"(a[3]), "r"(b[0]), "r"(b[1]));
}
__device__ __forceinline__ void bf16pair(float v, __nv_bfloat16& h, __nv_bfloat16& l) {
    h = __float2bfloat16(v);
    l = __float2bfloat16(v - __bfloat162float(h));
}

// ---------------- shared GEMM machinery ----------------
#define SKP 40
#define A_ARR (128 * SKP * 2)
#define B_ARR (64 * SKP * 2)
#define STAGE_B (2 * A_ARR + 2 * B_ARR)
#define NSTAGE 3

template<int NT>
__device__ __forceinline__ void gemm_load_stage(
    uint32_t stage, const __nv_bfloat16* Ah, const __nv_bfloat16* Al,
    const __nv_bfloat16* Bh, const __nv_bfloat16* Bl,
    int m0, int n0, int Ktot, int k0, int t, int ldk)
{
#pragma unroll
    for (int p = 0; p < 2; p++) {
        int id = t + p * 256;
        int r = id >> 2;
        cp_async16(stage + 0 * A_ARR + (uint32_t)(r * SKP + ldk) * 2,
                   Ah + (size_t)(m0 + r) * Ktot + k0 + ldk);
        cp_async16(stage + 1 * A_ARR + (uint32_t)(r * SKP + ldk) * 2,
                   Al + (size_t)(m0 + r) * Ktot + k0 + ldk);
    }
    {
        int r = t >> 2;
        cp_async16(stage + 2 * A_ARR + (uint32_t)(r * SKP + ldk) * 2,
                   Bh + (size_t)(n0 + r) * Ktot + k0 + ldk);
        if (NT == 3)
            cp_async16(stage + 2 * A_ARR + B_ARR + (uint32_t)(r * SKP + ldk) * 2,
                       Bl + (size_t)(n0 + r) * Ktot + k0 + ldk);
    }
}

template<int NT>
__device__ __forceinline__ void gemm_mainloop(
    uint32_t sb, const __nv_bfloat16* Ah, const __nv_bfloat16* Al,
    const __nv_bfloat16* Bh, const __nv_bfloat16* Bl,
    int m0, int n0, int Ktot, int t, float acc[2][4][4],
    uint32_t aRowOff, uint32_t bRowOff)
{
    const int ldk = (t & 3) * 8;
    const int nch = Ktot >> 5;

    gemm_load_stage<NT>(sb, Ah, Al, Bh, Bl, m0, n0, Ktot, 0, t, ldk);
    CP_COMMIT();
    if (nch > 1) gemm_load_stage<NT>(sb + STAGE_B, Ah, Al, Bh, Bl, m0, n0, Ktot, 32, t, ldk);
    CP_COMMIT();

    int sidx = 0;
    for (int c = 0; c < nch; c++) {
        CP_WAIT1();
        __syncthreads();

        if (c + 2 < nch) {
            int fidx = sidx + 2; if (fidx >= NSTAGE) fidx -= NSTAGE;
            gemm_load_stage<NT>(sb + fidx * STAGE_B, Ah, Al, Bh, Bl, m0, n0, Ktot, (c + 2) << 5, t, ldk);
        }
        CP_COMMIT();

        const uint32_t stage = sb + sidx * STAGE_B;
#pragma unroll
        for (int kk = 0; kk < 2; kk++) {
            const uint32_t kO = kk * 32;
            uint32_t aH[2][4], aL[2][4], bH[4][2], bL[4][2];
#pragma unroll
            for (int mt = 0; mt < 2; mt++) {
                ldsm4(aH[mt], stage + 0 * A_ARR + aRowOff + (uint32_t)(mt * 16 * SKP) * 2 + kO);
                ldsm4(aL[mt], stage + 1 * A_ARR + aRowOff + (uint32_t)(mt * 16 * SKP) * 2 + kO);
            }
#pragma unroll
            for (int nt2 = 0; nt2 < 2; nt2++) {
                uint32_t base = (uint32_t)((nt2 * 16) * SKP) * 2 + bRowOff + kO;
                ldsm4(&bH[nt2 * 2][0], stage + 2 * A_ARR + base);
                if (NT == 3) ldsm4(&bL[nt2 * 2][0], stage + 2 * A_ARR + B_ARR + base);
            }
#pragma unroll
            for (int mt = 0; mt < 2; mt++)
#pragma unroll
                for (int nt = 0; nt < 4; nt++)
                    mma16816(acc[mt][nt], aH[mt], bH[nt]);
#pragma unroll
            for (int mt = 0; mt < 2; mt++)
#pragma unroll
                for (int nt = 0; nt < 4; nt++)
                    mma16816(acc[mt][nt], aL[mt], bH[nt]);
            if (NT == 3) {
#pragma unroll
                for (int mt = 0; mt < 2; mt++)
#pragma unroll
                    for (int nt = 0; nt < 4; nt++)
                        mma16816(acc[mt][nt], aH[mt], bL[nt]);
            }
        }

        if (++sidx == NSTAGE) sidx = 0;
    }
}

// general GEMM; mode 0: fp32 out (+bias); mode 2: relu -> bf16 pair
template<int NT>
__global__ __launch_bounds__(256, 2)
void mma_gemm(const __nv_bfloat16* __restrict__ Ah, const __nv_bfloat16* __restrict__ Al,
              const __nv_bfloat16* __restrict__ Bh, const __nv_bfloat16* __restrict__ Bl,
              const float* __restrict__ bias,
              float* __restrict__ Cf, __nv_bfloat16* __restrict__ Ch, __nv_bfloat16* __restrict__ Cl,
              int Ktot, int ldc, int mode)
{
    extern __shared__ __align__(128) char smemc[];
    const uint32_t sb = smem_to_u32(smemc);
    const int t = threadIdx.x, w = t >> 5, lane = t & 31;
    const int m0 = blockIdx.y * 128, n0 = blockIdx.x * 64;
    const int wm = w & 3, wn = w >> 2;

    const uint32_t aRowOff = (uint32_t)((wm * 32 + (lane & 15)) * SKP + (lane >> 4) * 8) * 2;
    const uint32_t bRowOff = (uint32_t)((wn * 32 + (lane >> 4) * 8 + (lane & 7)) * SKP + ((lane >> 3) & 1) * 8) * 2;

    float acc[2][4][4];
#pragma unroll
    for (int i = 0; i < 2; i++)
#pragma unroll
        for (int j = 0; j < 4; j++)
#pragma unroll
            for (int x = 0; x < 4; x++) acc[i][j][x] = 0.f;

    gemm_mainloop<NT>(sb, Ah, Al, Bh, Bl, m0, n0, Ktot, t, acc, aRowOff, bRowOff);

    const int rbase = m0 + wm * 32 + (lane >> 2);
    const int cbase = n0 + wn * 32 + (lane & 3) * 2;
#pragma unroll
    for (int mt = 0; mt < 2; mt++)
#pragma unroll
        for (int half = 0; half < 2; half++) {
            const int m = rbase + mt * 16 + half * 8;
#pragma unroll
            for (int nt = 0; nt < 4; nt++) {
                const int n = cbase + nt * 8;
                float v0 = acc[mt][nt][half * 2 + 0];
                float v1 = acc[mt][nt][half * 2 + 1];
                if (bias) { v0 += bias[n]; v1 += bias[n + 1]; }
                if (mode == 2) {
                    v0 = fmaxf(v0, 0.f); v1 = fmaxf(v1, 0.f);
                    __nv_bfloat16 h0, l0, h1, l1;
                    bf16pair(v0, h0, l0); bf16pair(v1, h1, l1);
                    *(__nv_bfloat162*)(Ch + (size_t)m * ldc + n) = __nv_bfloat162(h0, h1);
                    *(__nv_bfloat162*)(Cl + (size_t)m * ldc + n) = __nv_bfloat162(l0, l1);
                } else {
                    *(float2*)(Cf + (size_t)m * ldc + n) = make_float2(v0, v1);
                }
            }
        }
}

// batched ov GEMM: o[bh][128x64] = a[bh][128x256] @ vT[bh][64x256]^T, 3-term, cat epilogue
__global__ __launch_bounds__(256, 2)
void attn_ov_mma(const __nv_bfloat16* __restrict__ a_h, const __nv_bfloat16* __restrict__ a_l,
                 const __nv_bfloat16* __restrict__ vTh, const __nv_bfloat16* __restrict__ vTl,
                 __nv_bfloat16* __restrict__ cath, __nv_bfloat16* __restrict__ catl)
{
    extern __shared__ __align__(128) char smemc[];
    const uint32_t sb = smem_to_u32(smemc);
    const int t = threadIdx.x, w = t >> 5, lane = t & 31;
    const int bh = blockIdx.x, it = blockIdx.y;
    const int b = bh >> 3, h = bh & 7;
    const int m0 = it * 128;
    const int wm = w & 3, wn = w >> 2;

    const __nv_bfloat16* Ah = a_h + (size_t)bh * 256 * 256;
    const __nv_bfloat16* Al = a_l + (size_t)bh * 256 * 256;
    const __nv_bfloat16* Bh = vTh + (size_t)bh * 64 * 256;
    const __nv_bfloat16* Bl = vTl + (size_t)bh * 64 * 256;

    const uint32_t aRowOff = (uint32_t)((wm * 32 + (lane & 15)) * SKP + (lane >> 4) * 8) * 2;
    const uint32_t bRowOff = (uint32_t)((wn * 32 + (lane >> 4) * 8 + (lane & 7)) * SKP + ((lane >> 3) & 1) * 8) * 2;

    float acc[2][4][4];
#pragma unroll
    for (int i = 0; i < 2; i++)
#pragma unroll
        for (int j = 0; j < 4; j++)
#pragma unroll
            for (int x = 0; x < 4; x++) acc[i][j][x] = 0.f;

    gemm_mainloop<3>(sb, Ah, Al, Bh, Bl, m0, 0, 256, t, acc, aRowOff, bRowOff);

    const int rbase = m0 + wm * 32 + (lane >> 2);
    const int cbase = wn * 32 + (lane & 3) * 2;
#pragma unroll
    for (int mt = 0; mt < 2; mt++)
#pragma unroll
        for (int half = 0; half < 2; half++) {
            const int i = rbase + mt * 16 + half * 8;
#pragma unroll
            for (int nt = 0; nt < 4; nt++) {
                const int d = cbase + nt * 8;
                size_t off = (size_t)(b * Nseq + i) * CATPAD + OPOFF + h * Dd + d;
                __nv_bfloat16 h0, l0, h1, l1;
                bf16pair(acc[mt][nt][half * 2 + 0], h0, l0);
                bf16pair(acc[mt][nt][half * 2 + 1], h1, l1);
                *(__nv_bfloat162*)(cath + off) = __nv_bfloat162(h0, h1);
                *(__nv_bfloat162*)(catl + off) = __nv_bfloat162(l0, l1);
            }
        }
}

// vT transpose-convert: fp32 v [row][1024 + h*64 + d] -> bf16 pair [bh][d][j]
__global__ __launch_bounds__(256)
void vT_cvt(const float* __restrict__ qkv,
            __nv_bfloat16* __restrict__ vTh, __nv_bfloat16* __restrict__ vTl)
{
    __shared__ float tile[64][33];
    const int bh = blockIdx.x, jb = blockIdx.y;
    const int b = bh >> 3, h = bh & 7;
    const int t = threadIdx.x;
    const int j0 = jb * 32;

    const float* vbase = qkv + (size_t)b * Nseq * 1536 + 1024 + h * 64;
#pragma unroll
    for (int p = 0; p < 8; p++) {
        int idx = t + p * 256;
        int j = idx >> 6, d = idx & 63;
        tile[d][j] = vbase[(size_t)(j0 + j) * 1536 + d];
    }
    __syncthreads();
#pragma unroll
    for (int p = 0; p < 8; p++) {
        int idx = t + p * 256;
        int d = idx >> 5, j = idx & 31;
        __nv_bfloat16 hh, ll; bf16pair(tile[d][j], hh, ll);
        size_t off = ((size_t)bh * 64 + d) * 256 + j0 + j;
        vTh[off] = hh; vTl[off] = ll;
    }
}

// ---------------- fused prep ----------------
struct PrepJob {
    const float* src; __nv_bfloat16 *dh, *dl;
    int K, Nn, Kpad, ktiles, perm, base; float scale;
};
struct PrepArgs {
    PrepJob j[6];
    const float4* s_src; __nv_bfloat162 *s_dh, *s_dl;
    __nv_bfloat16 *pad_h, *pad_l;
    int cvt_base, pad_base;
};

__global__ void prep_kernel(PrepArgs a)
{
    __shared__ float tile[32][33];
    const int bid = blockIdx.x;
    const int tx = threadIdx.x, ty = threadIdx.y;
    const int t = ty * 32 + tx;

    if (bid >= a.pad_base) {
        int idx = (bid - a.pad_base) * 256 + t;
        int row = idx / (CATPAD - CATC), col = idx % (CATPAD - CATC);
        if (row < ROWS) {
            a.pad_h[(size_t)row * CATPAD + CATC + col] = __float2bfloat16(0.f);
            a.pad_l[(size_t)row * CATPAD + CATC + col] = __float2bfloat16(0.f);
        }
        return;
    }
    if (bid >= a.cvt_base) {
        int i = (bid - a.cvt_base) * 256 + t;
        float4 v = a.s_src[i];
        __nv_bfloat16 hx, lx, hy, ly, hz, lz, hw, lw;
        bf16pair(v.x, hx, lx); bf16pair(v.y, hy, ly);
        bf16pair(v.z, hz, lz); bf16pair(v.w, hw, lw);
        a.s_dh[i * 2 + 0] = __nv_bfloat162(hx, hy); a.s_dh[i * 2 + 1] = __nv_bfloat162(hz, hw);
        a.s_dl[i * 2 + 0] = __nv_bfloat162(lx, ly); a.s_dl[i * 2 + 1] = __nv_bfloat162(lz, lw);
        return;
    }

    int ji = 0;
#pragma unroll
    for (int q = 1; q < 6; q++) if (bid >= a.j[q].base) ji = q;
    const PrepJob jb = a.j[ji];
    const int local = bid - jb.base;
    const int kt = local % jb.ktiles, ntl = local / jb.ktiles;
    const int k0 = kt * 32, n0 = ntl * 32;

#pragma unroll
    for (int j = 0; j < 4; j++) {
        int k = k0 + ty + j * 8;
        int n = n0 + tx;
        tile[tx][ty + j * 8] = (k < jb.K) ? jb.src[(size_t)k * jb.Nn + n] * jb.scale : 0.f;
    }
    __syncthreads();
#pragma unroll
    for (int j = 0; j < 4; j++) {
        int k = k0 + tx;
        int n = n0 + ty + j * 8;
        int nr = jb.perm ? (((n & 7) << 6) | (n >> 3)) : n;
        float v = tile[ty + j * 8][tx];
        __nv_bfloat16 h, l; bf16pair(v, h, l);
        jb.dh[(size_t)nr * jb.Kpad + k] = h;
        jb.dl[(size_t)nr * jb.Kpad + k] = l;
    }
}

// ---------------- attention softmax (register tiled; swizzled kT) ----------------
#define QSS 68

__global__ __launch_bounds__(256, 2)
void attn_softmax_kernel(const float* __restrict__ qkv, const float* __restrict__ wb,
                         float* __restrict__ a_out,
                         __nv_bfloat16* __restrict__ a_h, __nv_bfloat16* __restrict__ a_l,
                         __nv_bfloat16* __restrict__ cath, __nv_bfloat16* __restrict__ catl)
{
    extern __shared__ float sm[];
    float* qs   = sm;                 // [64][QSS]
    float* kT   = qs + 64 * QSS;      // [64][256] swizzled; reused as ls[64][256]
    float* wbs  = kT + 64 * 256;      // [68]
    float* pinv = wbs + 68;           // [64]
    float* p0   = pinv + 64;          // [64]
    float* p1   = p0 + 64;            // [64]

    const int bh = blockIdx.x, it = blockIdx.y;
    const int b = bh >> 3, h = bh & 7;
    const int t = threadIdx.x;
    const int tn = t & 15, tm = t >> 4;
    const int i0 = it * 64;

    const float* base = qkv + (size_t)b * Nseq * 1536 + h * 64;

#pragma unroll
    for (int p = 0; p < 4; p++) {
        int idx = t + p * 256;
        int r = idx >> 4, dg = idx & 15;
        float4 v = *(const float4*)(base + (size_t)(i0 + r) * 1536 + dg * 4);
        *(float4*)&qs[r * QSS + dg * 4] = v;
    }
    // fill kT transposed with XOR swizzle: element (d, j) at d*256 + ((j>>2)^(d>>2 & 15))*4 + (j&3)
    {
        const int dg = t & 15;        // d-group: rows dg*4..dg*4+3 (so d>>2 = dg)
#pragma unroll
        for (int p = 0; p < 16; p++) {
            int j = (t >> 4) + p * 16;
            float4 v = *(const float4*)(base + (size_t)j * 1536 + 512 + dg * 4);
            int pb = (((j >> 2) ^ dg) << 2) + (j & 3);
            kT[(dg * 4 + 0) * 256 + pb] = v.x;
            kT[(dg * 4 + 1) * 256 + pb] = v.y;
            kT[(dg * 4 + 2) * 256 + pb] = v.z;
            kT[(dg * 4 + 3) * 256 + pb] = v.w;
        }
    }
    if (t < NBb) wbs[t] = WLv * wb[t * Hh + h];
    __syncthreads();

    float acc[4][16];
#pragma unroll
    for (int x = 0; x < 4; x++)
#pragma unroll
        for (int u = 0; u < 16; u++) acc[x][u] = 0.f;

#pragma unroll 4
    for (int d = 0; d < 64; d++) {
        float a0 = qs[(tm * 4 + 0) * QSS + d];
        float a1 = qs[(tm * 4 + 1) * QSS + d];
        float a2 = qs[(tm * 4 + 2) * QSS + d];
        float a3 = qs[(tm * 4 + 3) * QSS + d];
        const int g = (d >> 2) & 15;
        const float* kr = &kT[d * 256];
        float4 b0 = *(const float4*)(kr + (((tn * 4 + 0) ^ g) << 2));
        float4 b1 = *(const float4*)(kr + (((tn * 4 + 1) ^ g) << 2));
        float4 b2 = *(const float4*)(kr + (((tn * 4 + 2) ^ g) << 2));
        float4 b3 = *(const float4*)(kr + (((tn * 4 + 3) ^ g) << 2));
        const float bv[16] = { b0.x,b0.y,b0.z,b0.w, b1.x,b1.y,b1.z,b1.w,
                               b2.x,b2.y,b2.z,b2.w, b3.x,b3.y,b3.z,b3.w };
#pragma unroll
        for (int u = 0; u < 16; u++) {
            acc[0][u] += a0 * bv[u];
            acc[1][u] += a1 * bv[u];
            acc[2][u] += a2 * bv[u];
            acc[3][u] += a3 * bv[u];
        }
    }

#pragma unroll
    for (int x = 0; x < 4; x++) {
        const int i = i0 + tm * 4 + x;
#pragma unroll
        for (int u = 0; u < 16; u++) {
            int c = i - (tn * 16 + u);
            c = (c < -32) ? -32 : (c > 32 ? 32 : c);
            acc[x][u] += wbs[c + 32];
        }
    }

    float inv4[4], s04[4], s14[4];
#pragma unroll
    for (int x = 0; x < 4; x++) {
        const int i = i0 + tm * 4 + x;
        float m = acc[x][0];
#pragma unroll
        for (int u = 1; u < 16; u++) m = fmaxf(m, acc[x][u]);
#pragma unroll
        for (int o = 1; o < 16; o <<= 1) m = fmaxf(m, __shfl_xor_sync(0xffffffffu, m, o));
        float se = 0.f, s0 = 0.f, s1 = 0.f;
#pragma unroll
        for (int u = 0; u < 16; u++) {
            float e = __expf(acc[x][u] - m);
            acc[x][u] = e;
            se += e;
            int j = tn * 16 + u;
            if (j >= i + 32) s0 += e;
            if (j <= i - 32) s1 += e;
        }
#pragma unroll
        for (int o = 1; o < 16; o <<= 1) {
            se += __shfl_xor_sync(0xffffffffu, se, o);
            s0 += __shfl_xor_sync(0xffffffffu, s0, o);
            s1 += __shfl_xor_sync(0xffffffffu, s1, o);
        }
        float inv = 1.f / se;
        inv4[x] = inv; s04[x] = s0 * inv; s14[x] = s1 * inv;
    }

    __syncthreads();   // kT reads done -> safe to overwrite as ls

    float* ls = kT;    // plain layout [r][256]
#pragma unroll
    for (int x = 0; x < 4; x++) {
        const int r = tm * 4 + x;
        const int i = i0 + r;
        const float inv = inv4[x];
        *(float4*)&ls[r * 256 + tn * 16 + 0]  = make_float4(acc[x][0], acc[x][1], acc[x][2], acc[x][3]);
        *(float4*)&ls[r * 256 + tn * 16 + 4]  = make_float4(acc[x][4], acc[x][5], acc[x][6], acc[x][7]);
        *(float4*)&ls[r * 256 + tn * 16 + 8]  = make_float4(acc[x][8], acc[x][9], acc[x][10], acc[x][11]);
        *(float4*)&ls[r * 256 + tn * 16 + 12] = make_float4(acc[x][12], acc[x][13], acc[x][14], acc[x][15]);
        float* ar = a_out + ((size_t)bh * 256 + i) * 256 + tn * 16;
        *(float4*)(ar + 0)  = make_float4(acc[x][0] * inv, acc[x][1] * inv, acc[x][2] * inv, acc[x][3] * inv);
        *(float4*)(ar + 4)  = make_float4(acc[x][4] * inv, acc[x][5] * inv, acc[x][6] * inv, acc[x][7] * inv);
        *(float4*)(ar + 8)  = make_float4(acc[x][8] * inv, acc[x][9] * inv, acc[x][10] * inv, acc[x][11] * inv);
        *(float4*)(ar + 12) = make_float4(acc[x][12] * inv, acc[x][13] * inv, acc[x][14] * inv, acc[x][15] * inv);
        if (tn == 0) { pinv[r] = inv; p0[r] = s04[x]; p1[r] = s14[x]; }
    }
    __syncthreads();

    // a bf16 hi/lo emission: r uniform per iteration -> broadcast pinv, coalesced LDS/STG
    for (int r = 0; r < 64; r++) {
        float aval = ls[r * 256 + t] * pinv[r];
        __nv_bfloat16 hh, ll; bf16pair(aval, hh, ll);
        size_t off = ((size_t)bh * 256 + i0 + r) * 256 + t;
        a_h[off] = hh; a_l[off] = ll;
    }

    // phase 3: all 256 threads cover 64 rows x 65 bins
#pragma unroll
    for (int p = 0; p < 17; p++) {
        int idx = t + p * 256;
        if (idx < 64 * NBb) {
            int r = idx / NBb, c = idx - r * NBb;
            const int i = i0 + r;
            float val;
            if (c == 0)       val = p0[r];
            else if (c == 64) val = p1[r];
            else {
                int j = i + 32 - c;
                val = (j >= 0 && j < 256) ? ls[r * 256 + j] * pinv[r] : 0.f;
            }
            __nv_bfloat16 hh, ll; bf16pair(val, hh, ll);
            size_t off = (size_t)(b * Nseq + i) * CATPAD + h * NBb + c;
            cath[off] = hh; catl[off] = ll;
        }
    }
}

// ---------------- layernorm ----------------
__global__ __launch_bounds__(256)
void ln_kernel(const float* __restrict__ xa, const float* __restrict__ xb,
               const float* __restrict__ g, const float* __restrict__ be,
               float* __restrict__ out, __nv_bfloat16* __restrict__ oh, __nv_bfloat16* __restrict__ ol)
{
    __shared__ float red[16];
    const int row = blockIdx.x, t = threadIdx.x;
    const float* pa = xa + (size_t)row * CS;
    const float* pb = xb + (size_t)row * CS;
    float x0 = pa[t] + pb[t];
    float x1 = pa[t + 256] + pb[t + 256];
    float s = x0 + x1, q = x0 * x0 + x1 * x1;
    const int lane = t & 31, w = t >> 5;
#pragma unroll
    for (int o = 16; o; o >>= 1) {
        s += __shfl_xor_sync(0xffffffffu, s, o);
        q += __shfl_xor_sync(0xffffffffu, q, o);
    }
    if (lane == 0) { red[w] = s; red[8 + w] = q; }
    __syncthreads();
    float S = 0.f, Q = 0.f;
#pragma unroll
    for (int u = 0; u < 8; u++) { S += red[u]; Q += red[8 + u]; }
    float mean = S * (1.f / 512.f);
    float var  = Q * (1.f / 512.f) - mean * mean;
    float rstd = rsqrtf(var + 1e-5f);
    float y0 = (x0 - mean) * rstd * g[t] + be[t];
    float y1 = (x1 - mean) * rstd * g[t + 256] + be[t + 256];
    out[(size_t)row * CS + t]       = y0;
    out[(size_t)row * CS + t + 256] = y1;
    if (oh) {
        __nv_bfloat16 h, l;
        bf16pair(y0, h, l); oh[(size_t)row * CS + t] = h;       ol[(size_t)row * CS + t] = l;
        bf16pair(y1, h, l); oh[(size_t)row * CS + t + 256] = h; ol[(size_t)row * CS + t + 256] = l;
    }
}

// ---------------- launch ----------------
extern "C" void kernel_launch(void* const* d_in, const int* in_sizes, int n_in,
                              void* d_out, int out_size)
{
    const float* s     = (const float*)d_in[0];
    const float* wq    = (const float*)d_in[2];
    const float* wk    = (const float*)d_in[3];
    const float* wv    = (const float*)d_in[4];
    const float* wb    = (const float*)d_in[5];
    const float* wo    = (const float*)d_in[6];
    const float* bo    = (const float*)d_in[7];
    const float* ln1g  = (const float*)d_in[8];
    const float* ln1b  = (const float*)d_in[9];
    const float* w1    = (const float*)d_in[10];
    const float* b1    = (const float*)d_in[11];
    const float* w2    = (const float*)d_in[12];
    const float* b2    = (const float*)d_in[13];
    const float* ln2g  = (const float*)d_in[14];
    const float* ln2b  = (const float*)d_in[15];

    float* out   = (float*)d_out;
    float* a_out = out + X_ELEMS;

    float *p_qkv, *p_embd, *p_x1, *p_ff2;
    __nv_bfloat16 *p_sh, *p_sl, *p_wqkvh, *p_wqkvl, *p_woh, *p_wol, *p_w1h, *p_w1l,
                  *p_w2h, *p_w2l, *p_cath, *p_catl, *p_x1h, *p_x1l, *p_ffh, *p_ffl,
                  *p_ah, *p_al, *p_vTh, *p_vTl;
    cudaGetSymbolAddress((void**)&p_qkv,   g_qkv);
    cudaGetSymbolAddress((void**)&p_embd,  g_embd);
    cudaGetSymbolAddress((void**)&p_x1,    g_x1);
    cudaGetSymbolAddress((void**)&p_ff2,   g_ff2);
    cudaGetSymbolAddress((void**)&p_sh,    g_sh);
    cudaGetSymbolAddress((void**)&p_sl,    g_sl);
    cudaGetSymbolAddress((void**)&p_wqkvh, g_wqkvT_h);
    cudaGetSymbolAddress((void**)&p_wqkvl, g_wqkvT_l);
    cudaGetSymbolAddress((void**)&p_woh,   g_woT_h);
    cudaGetSymbolAddress((void**)&p_wol,   g_woT_l);
    cudaGetSymbolAddress((void**)&p_w1h,   g_w1T_h);
    cudaGetSymbolAddress((void**)&p_w1l,   g_w1T_l);
    cudaGetSymbolAddress((void**)&p_w2h,   g_w2T_h);
    cudaGetSymbolAddress((void**)&p_w2l,   g_w2T_l);
    cudaGetSymbolAddress((void**)&p_cath,  g_cath);
    cudaGetSymbolAddress((void**)&p_catl,  g_catl);
    cudaGetSymbolAddress((void**)&p_x1h,   g_x1h);
    cudaGetSymbolAddress((void**)&p_x1l,   g_x1l);
    cudaGetSymbolAddress((void**)&p_ffh,   g_ffh);
    cudaGetSymbolAddress((void**)&p_ffl,   g_ffl);
    cudaGetSymbolAddress((void**)&p_ah,    g_ah);
    cudaGetSymbolAddress((void**)&p_al,    g_al);
    cudaGetSymbolAddress((void**)&p_vTh,   g_vTh);
    cudaGetSymbolAddress((void**)&p_vTl,   g_vTl);

    const int SM1 = (64 * QSS + 64 * 256 + 68 + 192) * 4;   // 83,984
    const int SMG = NSTAGE * STAGE_B;                        // 92,160
    cudaFuncSetAttribute(attn_softmax_kernel, cudaFuncAttributeMaxDynamicSharedMemorySize, SM1);
    cudaFuncSetAttribute(attn_ov_mma,         cudaFuncAttributeMaxDynamicSharedMemorySize, SMG);
    cudaFuncSetAttribute(mma_gemm<3>,         cudaFuncAttributeMaxDynamicSharedMemorySize, SMG);
    cudaFuncSetAttribute(mma_gemm<2>,         cudaFuncAttributeMaxDynamicSharedMemorySize, SMG);

    dim3 blk(256);

    // fused prep (ONE launch)
    PrepArgs pa;
    pa.j[0] = { wq, p_wqkvh,              p_wqkvl,              512,  512,  512, 16, 1, 0,    WLS };
    pa.j[1] = { wk, p_wqkvh + 512 * 512,  p_wqkvl + 512 * 512,  512,  512,  512, 16, 1, 256,  1.f };
    pa.j[2] = { wv, p_wqkvh + 1024 * 512, p_wqkvl + 1024 * 512, 512,  512,  512, 16, 1, 512,  1.f };
    pa.j[3] = { wo, p_woh,  p_wol,  CATC, 512,  CATPAD, 34, 0, 768,  1.f };
    pa.j[4] = { w1, p_w1h,  p_w1l,  512,  CT,   512,    16, 0, 1312, 1.f };
    pa.j[5] = { w2, p_w2h,  p_w2l,  CT,   512,  CT,     64, 0, 2336, 1.f };
    pa.s_src = (const float4*)s;
    pa.s_dh  = (__nv_bfloat162*)p_sh;
    pa.s_dl  = (__nv_bfloat162*)p_sl;
    pa.pad_h = p_cath; pa.pad_l = p_catl;
    pa.cvt_base = 3360;
    pa.pad_base = 3360 + 1024;
    prep_kernel<<<3360 + 1024 + 448, dim3(32, 8)>>>(pa);

    // qkv = s @ [wq|wk|wv]  — 2-term, clean fp32 epilogue
    mma_gemm<2><<<dim3(24, 16), blk, SMG>>>(p_sh, p_sl, p_wqkvh, p_wqkvl, nullptr,
                                            p_qkv, nullptr, nullptr, 512, 1536, 0);

    // vT = transpose-convert of v section (coalesced both sides)
    vT_cvt<<<dim3(64, 8), blk>>>(p_qkv, p_vTh, p_vTl);

    // attention: softmax (emits a fp32 + a bf16 pair + o_pair) then HMMA ov
    attn_softmax_kernel<<<dim3(Bq * Hh, 4), blk, SM1>>>(p_qkv, wb, a_out, p_ah, p_al, p_cath, p_catl);
    attn_ov_mma<<<dim3(Bq * Hh, 2), blk, SMG>>>(p_ah, p_al, p_vTh, p_vTl, p_cath, p_catl);

    // embd = cat @ wo + bo — 2-term
    mma_gemm<2><<<dim3(8, 16), blk, SMG>>>(p_cath, p_catl, p_woh, p_wol, bo,
                                           p_embd, nullptr, nullptr, CATPAD, 512, 0);

    // x1 = LN(s + embd)
    ln_kernel<<<ROWS, blk>>>(s, p_embd, ln1g, ln1b, p_x1, p_x1h, p_x1l);

    // ff = relu(x1 @ w1 + b1) — 2-term
    mma_gemm<2><<<dim3(32, 16), blk, SMG>>>(p_x1h, p_x1l, p_w1h, p_w1l, b1,
                                            nullptr, p_ffh, p_ffl, 512, CT, 2);

    // ff2 = ff @ w2 + b2 — 2-term
    mma_gemm<2><<<dim3(8, 16), blk, SMG>>>(p_ffh, p_ffl, p_w2h, p_w2l, b2,
                                           p_ff2, nullptr, nullptr, CT, 512, 0);

    // out = LN(x1 + ff2)
    ln_kernel<<<ROWS, blk>>>(p_x1, p_ff2, ln2g, ln2b, out, nullptr, nullptr);
}

// round 17
// speedup vs baseline: 1.2048x; 1.1102x over previous
#include <cuda_runtime.h>
#include <cuda_bf16.h>
#include <math.h>
#include <stdint.h>

// ---------------- problem constants ----------------
#define Bq   8
#define Nseq 256
#define CS   512
#define Hh   8
#define Dd   64
#define NBb  65
#define CT   2048
#define ROWS 2048
#define CATC 1032
#define CATPAD 1088
#define OPOFF 520
#define X_ELEMS (ROWS*CS)

static const float WLv = 0.70710678118654752440f;         // sqrt(0.5)
static const float WLS = 0.70710678118654752440f / 8.0f;  // WL / sqrt(D)

// ---------------- scratch (device globals; no allocation) ----------------
__device__ float g_qkv [ROWS * 1536];    // [row][ q|k|v ], col = h*64+d  (head-major)
__device__ float g_embd[ROWS * CS];
__device__ float g_x1  [ROWS * CS];
__device__ float g_ff2 [ROWS * CS];

__device__ __nv_bfloat16 g_sh   [ROWS * CS],      g_sl   [ROWS * CS];
__device__ __nv_bfloat16 g_wqkvT_h[1536 * CS],    g_wqkvT_l[1536 * CS];
__device__ __nv_bfloat16 g_woT_h [CS * CATPAD],   g_woT_l [CS * CATPAD];
__device__ __nv_bfloat16 g_w1T_h [CT * CS],       g_w1T_l [CT * CS];
__device__ __nv_bfloat16 g_w2T_h [CS * CT],       g_w2T_l [CS * CT];
__device__ __nv_bfloat16 g_cath  [ROWS * CATPAD], g_catl  [ROWS * CATPAD];
__device__ __nv_bfloat16 g_x1h   [ROWS * CS],     g_x1l   [ROWS * CS];
__device__ __nv_bfloat16 g_ffh   [ROWS * CT],     g_ffl   [ROWS * CT];
__device__ __nv_bfloat16 g_ah    [64 * 256 * 256], g_al   [64 * 256 * 256]; // a hi/lo [bh][i][j]
__device__ __nv_bfloat16 g_vTh   [64 * 64 * 256],  g_vTl  [64 * 64 * 256];  // vT hi/lo [bh][d][j]

// ---------------- low-level helpers ----------------
__device__ __forceinline__ uint32_t smem_to_u32(const void* p) {
    uint32_t a;
    asm("{ .reg .u64 t; cvta.to.shared.u64 t, %1; cvt.u32.u64 %0, t; }" : "=r"(a) : "l"(p));
    return a;
}
__device__ __forceinline__ void cp_async16(uint32_t dst, const void* src) {
    asm volatile("cp.async.cg.shared.global [%0], [%1], 16;" :: "r"(dst), "l"(src));
}
#define CP_COMMIT() asm volatile("cp.async.commit_group;" ::: "memory")
#define CP_WAIT1()  asm volatile("cp.async.wait_group 1;" ::: "memory")

__device__ __forceinline__ void ldsm4(uint32_t* r, uint32_t addr) {
    asm volatile("ldmatrix.sync.aligned.m8n8.x4.shared.b16 {%0,%1,%2,%3}, [%4];"
        : "=r"(r[0]), "=r"(r[1]), "=r"(r[2]), "=r"(r[3]) : "r"(addr));
}
__device__ __forceinline__ void mma16816(float* c, const uint32_t* a, const uint32_t* b) {
    asm volatile("mma.sync.aligned.m16n8k16.row.col.f32.bf16.bf16.f32 "
        "{%0,%1,%2,%3}, {%4,%5,%6,%7}, {%8,%9}, {%0,%1,%2,%3};"
        : "+f"(c[0]), "+f"(c[1]), "+f"(c[2]), "+f"(c[3])
        : "r"(a[0]), "r"(a[1]), "r"(a[2]), "r"(a[3]), "r"(b[0]), "r"(b[1]));
}
__device__ __forceinline__ void bf16pair(float v, __nv_bfloat16& h, __nv_bfloat16& l) {
    h = __float2bfloat16(v);
    l = __float2bfloat16(v - __bfloat162float(h));
}

// ---------------- shared GEMM machinery ----------------
#define SKP 40
#define A_ARR (128 * SKP * 2)
#define B_ARR (64 * SKP * 2)
#define STAGE_B (2 * A_ARR + 2 * B_ARR)
#define NSTAGE 3

template<int NT>
__device__ __forceinline__ void gemm_load_stage(
    uint32_t stage, const __nv_bfloat16* Ah, const __nv_bfloat16* Al,
    const __nv_bfloat16* Bh, const __nv_bfloat16* Bl,
    int m0, int n0, int Ktot, int k0, int t, int ldk)
{
#pragma unroll
    for (int p = 0; p < 2; p++) {
        int id = t + p * 256;
        int r = id >> 2;
        cp_async16(stage + 0 * A_ARR + (uint32_t)(r * SKP + ldk) * 2,
                   Ah + (size_t)(m0 + r) * Ktot + k0 + ldk);
        cp_async16(stage + 1 * A_ARR + (uint32_t)(r * SKP + ldk) * 2,
                   Al + (size_t)(m0 + r) * Ktot + k0 + ldk);
    }
    {
        int r = t >> 2;
        cp_async16(stage + 2 * A_ARR + (uint32_t)(r * SKP + ldk) * 2,
                   Bh + (size_t)(n0 + r) * Ktot + k0 + ldk);
        if (NT == 3)
            cp_async16(stage + 2 * A_ARR + B_ARR + (uint32_t)(r * SKP + ldk) * 2,
                       Bl + (size_t)(n0 + r) * Ktot + k0 + ldk);
    }
}

template<int NT>
__device__ __forceinline__ void gemm_mainloop(
    uint32_t sb, const __nv_bfloat16* Ah, const __nv_bfloat16* Al,
    const __nv_bfloat16* Bh, const __nv_bfloat16* Bl,
    int m0, int n0, int Ktot, int t, float acc[2][4][4],
    uint32_t aRowOff, uint32_t bRowOff)
{
    const int ldk = (t & 3) * 8;
    const int nch = Ktot >> 5;

    gemm_load_stage<NT>(sb, Ah, Al, Bh, Bl, m0, n0, Ktot, 0, t, ldk);
    CP_COMMIT();
    if (nch > 1) gemm_load_stage<NT>(sb + STAGE_B, Ah, Al, Bh, Bl, m0, n0, Ktot, 32, t, ldk);
    CP_COMMIT();

    int sidx = 0;
    for (int c = 0; c < nch; c++) {
        CP_WAIT1();
        __syncthreads();

        if (c + 2 < nch) {
            int fidx = sidx + 2; if (fidx >= NSTAGE) fidx -= NSTAGE;
            gemm_load_stage<NT>(sb + fidx * STAGE_B, Ah, Al, Bh, Bl, m0, n0, Ktot, (c + 2) << 5, t, ldk);
        }
        CP_COMMIT();

        const uint32_t stage = sb + sidx * STAGE_B;
#pragma unroll
        for (int kk = 0; kk < 2; kk++) {
            const uint32_t kO = kk * 32;
            uint32_t aH[2][4], aL[2][4], bH[4][2], bL[4][2];
#pragma unroll
            for (int mt = 0; mt < 2; mt++) {
                ldsm4(aH[mt], stage + 0 * A_ARR + aRowOff + (uint32_t)(mt * 16 * SKP) * 2 + kO);
                ldsm4(aL[mt], stage + 1 * A_ARR + aRowOff + (uint32_t)(mt * 16 * SKP) * 2 + kO);
            }
#pragma unroll
            for (int nt2 = 0; nt2 < 2; nt2++) {
                uint32_t base = (uint32_t)((nt2 * 16) * SKP) * 2 + bRowOff + kO;
                ldsm4(&bH[nt2 * 2][0], stage + 2 * A_ARR + base);
                if (NT == 3) ldsm4(&bL[nt2 * 2][0], stage + 2 * A_ARR + B_ARR + base);
            }
#pragma unroll
            for (int mt = 0; mt < 2; mt++)
#pragma unroll
                for (int nt = 0; nt < 4; nt++)
                    mma16816(acc[mt][nt], aH[mt], bH[nt]);
#pragma unroll
            for (int mt = 0; mt < 2; mt++)
#pragma unroll
                for (int nt = 0; nt < 4; nt++)
                    mma16816(acc[mt][nt], aL[mt], bH[nt]);
            if (NT == 3) {
#pragma unroll
                for (int mt = 0; mt < 2; mt++)
#pragma unroll
                    for (int nt = 0; nt < 4; nt++)
                        mma16816(acc[mt][nt], aH[mt], bL[nt]);
            }
        }

        if (++sidx == NSTAGE) sidx = 0;
    }
}

// general GEMM; mode 0: fp32 out (+bias); mode 2: relu -> bf16 pair
template<int NT>
__global__ __launch_bounds__(256, 2)
void mma_gemm(const __nv_bfloat16* __restrict__ Ah, const __nv_bfloat16* __restrict__ Al,
              const __nv_bfloat16* __restrict__ Bh, const __nv_bfloat16* __restrict__ Bl,
              const float* __restrict__ bias,
              float* __restrict__ Cf, __nv_bfloat16* __restrict__ Ch, __nv_bfloat16* __restrict__ Cl,
              int Ktot, int ldc, int mode)
{
    extern __shared__ __align__(128) char smemc[];
    const uint32_t sb = smem_to_u32(smemc);
    const int t = threadIdx.x, w = t >> 5, lane = t & 31;
    const int m0 = blockIdx.y * 128, n0 = blockIdx.x * 64;
    const int wm = w & 3, wn = w >> 2;

    const uint32_t aRowOff = (uint32_t)((wm * 32 + (lane & 15)) * SKP + (lane >> 4) * 8) * 2;
    const uint32_t bRowOff = (uint32_t)((wn * 32 + (lane >> 4) * 8 + (lane & 7)) * SKP + ((lane >> 3) & 1) * 8) * 2;

    float acc[2][4][4];
#pragma unroll
    for (int i = 0; i < 2; i++)
#pragma unroll
        for (int j = 0; j < 4; j++)
#pragma unroll
            for (int x = 0; x < 4; x++) acc[i][j][x] = 0.f;

    gemm_mainloop<NT>(sb, Ah, Al, Bh, Bl, m0, n0, Ktot, t, acc, aRowOff, bRowOff);

    const int rbase = m0 + wm * 32 + (lane >> 2);
    const int cbase = n0 + wn * 32 + (lane & 3) * 2;
#pragma unroll
    for (int mt = 0; mt < 2; mt++)
#pragma unroll
        for (int half = 0; half < 2; half++) {
            const int m = rbase + mt * 16 + half * 8;
#pragma unroll
            for (int nt = 0; nt < 4; nt++) {
                const int n = cbase + nt * 8;
                float v0 = acc[mt][nt][half * 2 + 0];
                float v1 = acc[mt][nt][half * 2 + 1];
                if (bias) { v0 += bias[n]; v1 += bias[n + 1]; }
                if (mode == 2) {
                    v0 = fmaxf(v0, 0.f); v1 = fmaxf(v1, 0.f);
                    __nv_bfloat16 h0, l0, h1, l1;
                    bf16pair(v0, h0, l0); bf16pair(v1, h1, l1);
                    *(__nv_bfloat162*)(Ch + (size_t)m * ldc + n) = __nv_bfloat162(h0, h1);
                    *(__nv_bfloat162*)(Cl + (size_t)m * ldc + n) = __nv_bfloat162(l0, l1);
                } else {
                    *(float2*)(Cf + (size_t)m * ldc + n) = make_float2(v0, v1);
                }
            }
        }
}

// batched ov GEMM: o[bh][128x64] = a[bh][128x256] @ vT[bh][64x256]^T, 3-term, cat epilogue
__global__ __launch_bounds__(256, 2)
void attn_ov_mma(const __nv_bfloat16* __restrict__ a_h, const __nv_bfloat16* __restrict__ a_l,
                 const __nv_bfloat16* __restrict__ vTh, const __nv_bfloat16* __restrict__ vTl,
                 __nv_bfloat16* __restrict__ cath, __nv_bfloat16* __restrict__ catl)
{
    extern __shared__ __align__(128) char smemc[];
    const uint32_t sb = smem_to_u32(smemc);
    const int t = threadIdx.x, w = t >> 5, lane = t & 31;
    const int bh = blockIdx.x, it = blockIdx.y;
    const int b = bh >> 3, h = bh & 7;
    const int m0 = it * 128;
    const int wm = w & 3, wn = w >> 2;

    const __nv_bfloat16* Ah = a_h + (size_t)bh * 256 * 256;
    const __nv_bfloat16* Al = a_l + (size_t)bh * 256 * 256;
    const __nv_bfloat16* Bh = vTh + (size_t)bh * 64 * 256;
    const __nv_bfloat16* Bl = vTl + (size_t)bh * 64 * 256;

    const uint32_t aRowOff = (uint32_t)((wm * 32 + (lane & 15)) * SKP + (lane >> 4) * 8) * 2;
    const uint32_t bRowOff = (uint32_t)((wn * 32 + (lane >> 4) * 8 + (lane & 7)) * SKP + ((lane >> 3) & 1) * 8) * 2;

    float acc[2][4][4];
#pragma unroll
    for (int i = 0; i < 2; i++)
#pragma unroll
        for (int j = 0; j < 4; j++)
#pragma unroll
            for (int x = 0; x < 4; x++) acc[i][j][x] = 0.f;

    gemm_mainloop<3>(sb, Ah, Al, Bh, Bl, m0, 0, 256, t, acc, aRowOff, bRowOff);

    const int rbase = m0 + wm * 32 + (lane >> 2);
    const int cbase = wn * 32 + (lane & 3) * 2;
#pragma unroll
    for (int mt = 0; mt < 2; mt++)
#pragma unroll
        for (int half = 0; half < 2; half++) {
            const int i = rbase + mt * 16 + half * 8;
#pragma unroll
            for (int nt = 0; nt < 4; nt++) {
                const int d = cbase + nt * 8;
                size_t off = (size_t)(b * Nseq + i) * CATPAD + OPOFF + h * Dd + d;
                __nv_bfloat16 h0, l0, h1, l1;
                bf16pair(acc[mt][nt][half * 2 + 0], h0, l0);
                bf16pair(acc[mt][nt][half * 2 + 1], h1, l1);
                *(__nv_bfloat162*)(cath + off) = __nv_bfloat162(h0, h1);
                *(__nv_bfloat162*)(catl + off) = __nv_bfloat162(l0, l1);
            }
        }
}

// vT transpose-convert: fp32 v [row][1024 + h*64 + d] -> bf16 pair [bh][d][j]
__global__ __launch_bounds__(256)
void vT_cvt(const float* __restrict__ qkv,
            __nv_bfloat16* __restrict__ vTh, __nv_bfloat16* __restrict__ vTl)
{
    __shared__ float tile[64][33];
    const int bh = blockIdx.x, jb = blockIdx.y;
    const int b = bh >> 3, h = bh & 7;
    const int t = threadIdx.x;
    const int j0 = jb * 32;

    const float* vbase = qkv + (size_t)b * Nseq * 1536 + 1024 + h * 64;
#pragma unroll
    for (int p = 0; p < 8; p++) {
        int idx = t + p * 256;
        int j = idx >> 6, d = idx & 63;
        tile[d][j] = vbase[(size_t)(j0 + j) * 1536 + d];
    }
    __syncthreads();
#pragma unroll
    for (int p = 0; p < 8; p++) {
        int idx = t + p * 256;
        int d = idx >> 5, j = idx & 31;
        __nv_bfloat16 hh, ll; bf16pair(tile[d][j], hh, ll);
        size_t off = ((size_t)bh * 64 + d) * 256 + j0 + j;
        vTh[off] = hh; vTl[off] = ll;
    }
}

// ---------------- fused prep ----------------
struct PrepJob {
    const float* src; __nv_bfloat16 *dh, *dl;
    int K, Nn, Kpad, ktiles, perm, base; float scale;
};
struct PrepArgs {
    PrepJob j[6];
    const float4* s_src; __nv_bfloat162 *s_dh, *s_dl;
    __nv_bfloat16 *pad_h, *pad_l;
    int cvt_base, pad_base;
};

__global__ void prep_kernel(PrepArgs a)
{
    __shared__ float tile[32][33];
    const int bid = blockIdx.x;
    const int tx = threadIdx.x, ty = threadIdx.y;
    const int t = ty * 32 + tx;

    if (bid >= a.pad_base) {
        int idx = (bid - a.pad_base) * 256 + t;
        int row = idx / (CATPAD - CATC), col = idx % (CATPAD - CATC);
        if (row < ROWS) {
            a.pad_h[(size_t)row * CATPAD + CATC + col] = __float2bfloat16(0.f);
            a.pad_l[(size_t)row * CATPAD + CATC + col] = __float2bfloat16(0.f);
        }
        return;
    }
    if (bid >= a.cvt_base) {
        int i = (bid - a.cvt_base) * 256 + t;
        float4 v = a.s_src[i];
        __nv_bfloat16 hx, lx, hy, ly, hz, lz, hw, lw;
        bf16pair(v.x, hx, lx); bf16pair(v.y, hy, ly);
        bf16pair(v.z, hz, lz); bf16pair(v.w, hw, lw);
        a.s_dh[i * 2 + 0] = __nv_bfloat162(hx, hy); a.s_dh[i * 2 + 1] = __nv_bfloat162(hz, hw);
        a.s_dl[i * 2 + 0] = __nv_bfloat162(lx, ly); a.s_dl[i * 2 + 1] = __nv_bfloat162(lz, lw);
        return;
    }

    int ji = 0;
#pragma unroll
    for (int q = 1; q < 6; q++) if (bid >= a.j[q].base) ji = q;
    const PrepJob jb = a.j[ji];
    const int local = bid - jb.base;
    const int kt = local % jb.ktiles, ntl = local / jb.ktiles;
    const int k0 = kt * 32, n0 = ntl * 32;

#pragma unroll
    for (int j = 0; j < 4; j++) {
        int k = k0 + ty + j * 8;
        int n = n0 + tx;
        tile[tx][ty + j * 8] = (k < jb.K) ? jb.src[(size_t)k * jb.Nn + n] * jb.scale : 0.f;
    }
    __syncthreads();
#pragma unroll
    for (int j = 0; j < 4; j++) {
        int k = k0 + tx;
        int n = n0 + ty + j * 8;
        int nr = jb.perm ? (((n & 7) << 6) | (n >> 3)) : n;
        float v = tile[ty + j * 8][tx];
        __nv_bfloat16 h, l; bf16pair(v, h, l);
        jb.dh[(size_t)nr * jb.Kpad + k] = h;
        jb.dl[(size_t)nr * jb.Kpad + k] = l;
    }
}

// ---------------- attention softmax (register tiled; swizzled kT, spread columns) ----------------
#define QSS 68

__global__ __launch_bounds__(256, 2)
void attn_softmax_kernel(const float* __restrict__ qkv, const float* __restrict__ wb,
                         float* __restrict__ a_out,
                         __nv_bfloat16* __restrict__ a_h, __nv_bfloat16* __restrict__ a_l,
                         __nv_bfloat16* __restrict__ cath, __nv_bfloat16* __restrict__ catl)
{
    extern __shared__ float sm[];
    float* qs   = sm;                 // [64][QSS]
    float* kT   = qs + 64 * QSS;      // [64][256] swizzled; reused as ls[64][256]
    float* wbs  = kT + 64 * 256;      // [68]
    float* pinv = wbs + 68;           // [64]
    float* p0   = pinv + 64;          // [64]
    float* p1   = p0 + 64;            // [64]

    const int bh = blockIdx.x, it = blockIdx.y;
    const int b = bh >> 3, h = bh & 7;
    const int t = threadIdx.x;
    const int tn = t & 15, tm = t >> 4;
    const int i0 = it * 64;

    const float* base = qkv + (size_t)b * Nseq * 1536 + h * 64;

#pragma unroll
    for (int p = 0; p < 4; p++) {
        int idx = t + p * 256;
        int r = idx >> 4, dg = idx & 15;
        float4 v = *(const float4*)(base + (size_t)(i0 + r) * 1536 + dg * 4);
        *(float4*)&qs[r * QSS + dg * 4] = v;
    }
    // fill kT transposed, XOR-swizzled: element (d, j) at d*256 + (((j>>2) ^ (d>>2 & 15)) << 2) + (j&3)
    {
        const int dg = t & 15;
#pragma unroll
        for (int p = 0; p < 16; p++) {
            int j = (t >> 4) + p * 16;
            float4 v = *(const float4*)(base + (size_t)j * 1536 + 512 + dg * 4);
            int pb = (((j >> 2) ^ dg) << 2) + (j & 3);
            kT[(dg * 4 + 0) * 256 + pb] = v.x;
            kT[(dg * 4 + 1) * 256 + pb] = v.y;
            kT[(dg * 4 + 2) * 256 + pb] = v.z;
            kT[(dg * 4 + 3) * 256 + pb] = v.w;
        }
    }
    if (t < NBb) wbs[t] = WLv * wb[t * Hh + h];
    __syncthreads();

    // thread tn owns columns j = u4*64 + tn*4 + e  (u = u4*4 + e)
    float acc[4][16];
#pragma unroll
    for (int x = 0; x < 4; x++)
#pragma unroll
        for (int u = 0; u < 16; u++) acc[x][u] = 0.f;

#pragma unroll 4
    for (int d = 0; d < 64; d++) {
        float a0 = qs[(tm * 4 + 0) * QSS + d];
        float a1 = qs[(tm * 4 + 1) * QSS + d];
        float a2 = qs[(tm * 4 + 2) * QSS + d];
        float a3 = qs[(tm * 4 + 3) * QSS + d];
        const int g = (d >> 2) & 15;
        const float* kr = &kT[d * 256];
        float4 b0 = *(const float4*)(kr + (((tn +  0) ^ g) << 2));
        float4 b1 = *(const float4*)(kr + (((tn + 16) ^ g) << 2));
        float4 b2 = *(const float4*)(kr + (((tn + 32) ^ g) << 2));
        float4 b3 = *(const float4*)(kr + (((tn + 48) ^ g) << 2));
        const float bv[16] = { b0.x,b0.y,b0.z,b0.w, b1.x,b1.y,b1.z,b1.w,
                               b2.x,b2.y,b2.z,b2.w, b3.x,b3.y,b3.z,b3.w };
#pragma unroll
        for (int u = 0; u < 16; u++) {
            acc[0][u] += a0 * bv[u];
            acc[1][u] += a1 * bv[u];
            acc[2][u] += a2 * bv[u];
            acc[3][u] += a3 * bv[u];
        }
    }

#pragma unroll
    for (int x = 0; x < 4; x++) {
        const int i = i0 + tm * 4 + x;
#pragma unroll
        for (int u = 0; u < 16; u++) {
            int j = ((u >> 2) << 6) + tn * 4 + (u & 3);
            int c = i - j;
            c = (c < -32) ? -32 : (c > 32 ? 32 : c);
            acc[x][u] += wbs[c + 32];
        }
    }

    float inv4[4], s04[4], s14[4];
#pragma unroll
    for (int x = 0; x < 4; x++) {
        const int i = i0 + tm * 4 + x;
        float m = acc[x][0];
#pragma unroll
        for (int u = 1; u < 16; u++) m = fmaxf(m, acc[x][u]);
#pragma unroll
        for (int o = 1; o < 16; o <<= 1) m = fmaxf(m, __shfl_xor_sync(0xffffffffu, m, o));
        float se = 0.f, s0 = 0.f, s1 = 0.f;
#pragma unroll
        for (int u = 0; u < 16; u++) {
            float e = __expf(acc[x][u] - m);
            acc[x][u] = e;
            se += e;
            int j = ((u >> 2) << 6) + tn * 4 + (u & 3);
            if (j >= i + 32) s0 += e;
            if (j <= i - 32) s1 += e;
        }
#pragma unroll
        for (int o = 1; o < 16; o <<= 1) {
            se += __shfl_xor_sync(0xffffffffu, se, o);
            s0 += __shfl_xor_sync(0xffffffffu, s0, o);
            s1 += __shfl_xor_sync(0xffffffffu, s1, o);
        }
        float inv = 1.f / se;
        inv4[x] = inv; s04[x] = s0 * inv; s14[x] = s1 * inv;
    }

    __syncthreads();   // kT reads done -> safe to overwrite as ls

    float* ls = kT;    // plain layout [r][256]
#pragma unroll
    for (int x = 0; x < 4; x++) {
        const int r = tm * 4 + x;
        const int i = i0 + r;
        const float inv = inv4[x];
        float* ar = a_out + ((size_t)bh * 256 + i) * 256;
#pragma unroll
        for (int u4 = 0; u4 < 4; u4++) {
            const int jb4 = u4 * 64 + tn * 4;
            *(float4*)&ls[r * 256 + jb4] = make_float4(acc[x][u4*4+0], acc[x][u4*4+1],
                                                       acc[x][u4*4+2], acc[x][u4*4+3]);
            *(float4*)(ar + jb4) = make_float4(acc[x][u4*4+0] * inv, acc[x][u4*4+1] * inv,
                                               acc[x][u4*4+2] * inv, acc[x][u4*4+3] * inv);
        }
        if (tn == 0) { pinv[r] = inv; p0[r] = s04[x]; p1[r] = s14[x]; }
    }
    __syncthreads();

    // a bf16 hi/lo emission: coalesced
    for (int r = 0; r < 64; r++) {
        float aval = ls[r * 256 + t] * pinv[r];
        __nv_bfloat16 hh, ll; bf16pair(aval, hh, ll);
        size_t off = ((size_t)bh * 256 + i0 + r) * 256 + t;
        a_h[off] = hh; a_l[off] = ll;
    }

    // phase 3: all 256 threads cover 64 rows x 65 bins
#pragma unroll
    for (int p = 0; p < 17; p++) {
        int idx = t + p * 256;
        if (idx < 64 * NBb) {
            int r = idx / NBb, c = idx - r * NBb;
            const int i = i0 + r;
            float val;
            if (c == 0)       val = p0[r];
            else if (c == 64) val = p1[r];
            else {
                int j = i + 32 - c;
                val = (j >= 0 && j < 256) ? ls[r * 256 + j] * pinv[r] : 0.f;
            }
            __nv_bfloat16 hh, ll; bf16pair(val, hh, ll);
            size_t off = (size_t)(b * Nseq + i) * CATPAD + h * NBb + c;
            cath[off] = hh; catl[off] = ll;
        }
    }
}

// ---------------- layernorm ----------------
__global__ __launch_bounds__(256)
void ln_kernel(const float* __restrict__ xa, const float* __restrict__ xb,
               const float* __restrict__ g, const float* __restrict__ be,
               float* __restrict__ out, __nv_bfloat16* __restrict__ oh, __nv_bfloat16* __restrict__ ol)
{
    __shared__ float red[16];
    const int row = blockIdx.x, t = threadIdx.x;
    const float* pa = xa + (size_t)row * CS;
    const float* pb = xb + (size_t)row * CS;
    float x0 = pa[t] + pb[t];
    float x1 = pa[t + 256] + pb[t + 256];
    float s = x0 + x1, q = x0 * x0 + x1 * x1;
    const int lane = t & 31, w = t >> 5;
#pragma unroll
    for (int o = 16; o; o >>= 1) {
        s += __shfl_xor_sync(0xffffffffu, s, o);
        q += __shfl_xor_sync(0xffffffffu, q, o);
    }
    if (lane == 0) { red[w] = s; red[8 + w] = q; }
    __syncthreads();
    float S = 0.f, Q = 0.f;
#pragma unroll
    for (int u = 0; u < 8; u++) { S += red[u]; Q += red[8 + u]; }
    float mean = S * (1.f / 512.f);
    float var  = Q * (1.f / 512.f) - mean * mean;
    float rstd = rsqrtf(var + 1e-5f);
    float y0 = (x0 - mean) * rstd * g[t] + be[t];
    float y1 = (x1 - mean) * rstd * g[t + 256] + be[t + 256];
    out[(size_t)row * CS + t]       = y0;
    out[(size_t)row * CS + t + 256] = y1;
    if (oh) {
        __nv_bfloat16 h, l;
        bf16pair(y0, h, l); oh[(size_t)row * CS + t] = h;       ol[(size_t)row * CS + t] = l;
        bf16pair(y1, h, l); oh[(size_t)row * CS + t + 256] = h; ol[(size_t)row * CS + t + 256] = l;
    }
}

// ---------------- launch ----------------
extern "C" void kernel_launch(void* const* d_in, const int* in_sizes, int n_in,
                              void* d_out, int out_size)
{
    const float* s     = (const float*)d_in[0];
    const float* wq    = (const float*)d_in[2];
    const float* wk    = (const float*)d_in[3];
    const float* wv    = (const float*)d_in[4];
    const float* wb    = (const float*)d_in[5];
    const float* wo    = (const float*)d_in[6];
    const float* bo    = (const float*)d_in[7];
    const float* ln1g  = (const float*)d_in[8];
    const float* ln1b  = (const float*)d_in[9];
    const float* w1    = (const float*)d_in[10];
    const float* b1    = (const float*)d_in[11];
    const float* w2    = (const float*)d_in[12];
    const float* b2    = (const float*)d_in[13];
    const float* ln2g  = (const float*)d_in[14];
    const float* ln2b  = (const float*)d_in[15];

    float* out   = (float*)d_out;
    float* a_out = out + X_ELEMS;

    float *p_qkv, *p_embd, *p_x1, *p_ff2;
    __nv_bfloat16 *p_sh, *p_sl, *p_wqkvh, *p_wqkvl, *p_woh, *p_wol, *p_w1h, *p_w1l,
                  *p_w2h, *p_w2l, *p_cath, *p_catl, *p_x1h, *p_x1l, *p_ffh, *p_ffl,
                  *p_ah, *p_al, *p_vTh, *p_vTl;
    cudaGetSymbolAddress((void**)&p_qkv,   g_qkv);
    cudaGetSymbolAddress((void**)&p_embd,  g_embd);
    cudaGetSymbolAddress((void**)&p_x1,    g_x1);
    cudaGetSymbolAddress((void**)&p_ff2,   g_ff2);
    cudaGetSymbolAddress((void**)&p_sh,    g_sh);
    cudaGetSymbolAddress((void**)&p_sl,    g_sl);
    cudaGetSymbolAddress((void**)&p_wqkvh, g_wqkvT_h);
    cudaGetSymbolAddress((void**)&p_wqkvl, g_wqkvT_l);
    cudaGetSymbolAddress((void**)&p_woh,   g_woT_h);
    cudaGetSymbolAddress((void**)&p_wol,   g_woT_l);
    cudaGetSymbolAddress((void**)&p_w1h,   g_w1T_h);
    cudaGetSymbolAddress((void**)&p_w1l,   g_w1T_l);
    cudaGetSymbolAddress((void**)&p_w2h,   g_w2T_h);
    cudaGetSymbolAddress((void**)&p_w2l,   g_w2T_l);
    cudaGetSymbolAddress((void**)&p_cath,  g_cath);
    cudaGetSymbolAddress((void**)&p_catl,  g_catl);
    cudaGetSymbolAddress((void**)&p_x1h,   g_x1h);
    cudaGetSymbolAddress((void**)&p_x1l,   g_x1l);
    cudaGetSymbolAddress((void**)&p_ffh,   g_ffh);
    cudaGetSymbolAddress((void**)&p_ffl,   g_ffl);
    cudaGetSymbolAddress((void**)&p_ah,    g_ah);
    cudaGetSymbolAddress((void**)&p_al,    g_al);
    cudaGetSymbolAddress((void**)&p_vTh,   g_vTh);
    cudaGetSymbolAddress((void**)&p_vTl,   g_vTl);

    const int SM1 = (64 * QSS + 64 * 256 + 68 + 192) * 4;   // 83,984
    const int SMG = NSTAGE * STAGE_B;                        // 92,160
    cudaFuncSetAttribute(attn_softmax_kernel, cudaFuncAttributeMaxDynamicSharedMemorySize, SM1);
    cudaFuncSetAttribute(attn_ov_mma,         cudaFuncAttributeMaxDynamicSharedMemorySize, SMG);
    cudaFuncSetAttribute(mma_gemm<3>,         cudaFuncAttributeMaxDynamicSharedMemorySize, SMG);
    cudaFuncSetAttribute(mma_gemm<2>,         cudaFuncAttributeMaxDynamicSharedMemorySize, SMG);

    dim3 blk(256);

    // fused prep (ONE launch)
    PrepArgs pa;
    pa.j[0] = { wq, p_wqkvh,              p_wqkvl,              512,  512,  512, 16, 1, 0,    WLS };
    pa.j[1] = { wk, p_wqkvh + 512 * 512,  p_wqkvl + 512 * 512,  512,  512,  512, 16, 1, 256,  1.f };
    pa.j[2] = { wv, p_wqkvh + 1024 * 512, p_wqkvl + 1024 * 512, 512,  512,  512, 16, 1, 512,  1.f };
    pa.j[3] = { wo, p_woh,  p_wol,  CATC, 512,  CATPAD, 34, 0, 768,  1.f };
    pa.j[4] = { w1, p_w1h,  p_w1l,  512,  CT,   512,    16, 0, 1312, 1.f };
    pa.j[5] = { w2, p_w2h,  p_w2l,  CT,   512,  CT,     64, 0, 2336, 1.f };
    pa.s_src = (const float4*)s;
    pa.s_dh  = (__nv_bfloat162*)p_sh;
    pa.s_dl  = (__nv_bfloat162*)p_sl;
    pa.pad_h = p_cath; pa.pad_l = p_catl;
    pa.cvt_base = 3360;
    pa.pad_base = 3360 + 1024;
    prep_kernel<<<3360 + 1024 + 448, dim3(32, 8)>>>(pa);

    // qkv = s @ [wq|wk|wv]  — 2-term, clean fp32 epilogue
    mma_gemm<2><<<dim3(24, 16), blk, SMG>>>(p_sh, p_sl, p_wqkvh, p_wqkvl, nullptr,
                                            p_qkv, nullptr, nullptr, 512, 1536, 0);

    // vT = transpose-convert of v section (coalesced both sides)
    vT_cvt<<<dim3(64, 8), blk>>>(p_qkv, p_vTh, p_vTl);

    // attention: softmax (emits a fp32 + a bf16 pair + o_pair) then HMMA ov
    attn_softmax_kernel<<<dim3(Bq * Hh, 4), blk, SM1>>>(p_qkv, wb, a_out, p_ah, p_al, p_cath, p_catl);
    attn_ov_mma<<<dim3(Bq * Hh, 2), blk, SMG>>>(p_ah, p_al, p_vTh, p_vTl, p_cath, p_catl);

    // embd = cat @ wo + bo — 2-term
    mma_gemm<2><<<dim3(8, 16), blk, SMG>>>(p_cath, p_catl, p_woh, p_wol, bo,
                                           p_embd, nullptr, nullptr, CATPAD, 512, 0);

    // x1 = LN(s + embd)
    ln_kernel<<<ROWS, blk>>>(s, p_embd, ln1g, ln1b, p_x1, p_x1h, p_x1l);

    // ff = relu(x1 @ w1 + b1) — 2-term
    mma_gemm<2><<<dim3(32, 16), blk, SMG>>>(p_x1h, p_x1l, p_w1h, p_w1l, b1,
                                            nullptr, p_ffh, p_ffl, 512, CT, 2);

    // ff2 = ff @ w2 + b2 — 2-term
    mma_gemm<2><<<dim3(8, 16), blk, SMG>>>(p_ffh, p_ffl, p_w2h, p_w2l, b2,
                                           p_ff2, nullptr, nullptr, CT, 512, 0);

    // out = LN(x1 + ff2)
    ln_kernel<<<ROWS, blk>>>(p_x1, p_ff2, ln2g, ln2b, out, nullptr, nullptr);
}